// round 10
// baseline (speedup 1.0000x reference)
#include <cuda_runtime.h>
#include <cuda_bf16.h>
#include <cstdint>

#define N_MAX 100000
#define E_MAX 1700000
#define D 128
#define BB 1024                 // build-kernel block size
#define NB_MAX 128              // >= ceil(N_MAX/BB) = 98

// ---------------- scratch (static device globals) ----------------
__device__ __align__(16) float g_buf[N_MAX * D];            // g[u] = dinv[u]*(X@W)[u]
__device__ __align__(16) __nv_bfloat16 g_xh[N_MAX * D];     // activation hi split (GEMM input)
__device__ __align__(16) __nv_bfloat16 g_xl[N_MAX * D];     // activation lo split
__device__ float g_dinv[N_MAX];
__device__ int   g_cnt[N_MAX];
__device__ int   g_rowptr[N_MAX + 1];
__device__ int   g_cursor[N_MAX];
__device__ int   g_blocksum[NB_MAX];
__device__ int   g_blockoff[NB_MAX];
__device__ int   g_csr[E_MAX];
__device__ __align__(16) __nv_bfloat16 g_wt_hi[3 * D * D];  // W^T hi split, [l][n][k]
__device__ __align__(16) __nv_bfloat16 g_wt_lo[3 * D * D];  // W^T lo split
__device__ unsigned g_bar_cnt = 0;
__device__ unsigned g_bar_gen = 0;

// ---------------- helpers ----------------
__device__ __forceinline__ uint32_t smem_u32(const void* p) {
    uint32_t a;
    asm("{ .reg .u64 t; cvta.to.shared.u64 t, %1; cvt.u32.u64 %0, t; }" : "=r"(a) : "l"(p));
    return a;
}
__device__ __forceinline__ void cp_async16(uint32_t saddr, const void* gptr, bool valid) {
    int sz = valid ? 16 : 0;
    asm volatile("cp.async.cg.shared.global [%0], [%1], 16, %2;"
                 :: "r"(saddr), "l"(gptr), "r"(sz));
}
#define CP_COMMIT()   asm volatile("cp.async.commit_group;")
#define CP_WAIT_ALL() asm volatile("cp.async.wait_all;" ::: "memory")

// sense-reversing grid barrier; safe with single-wave residency (nblocks <= #SMs)
__device__ __forceinline__ void grid_barrier(int nblocks) {
    __syncthreads();
    if (threadIdx.x == 0) {
        unsigned gen = atomicAdd(&g_bar_gen, 0u);
        __threadfence();
        unsigned old = atomicAdd(&g_bar_cnt, 1u);
        if (old == (unsigned)nblocks - 1u) {
            atomicExch(&g_bar_cnt, 0u);
            __threadfence();
            atomicAdd(&g_bar_gen, 1u);
        } else {
            while (atomicAdd(&g_bar_gen, 0u) == gen) { }
        }
        __threadfence();
    }
    __syncthreads();
}

__device__ __forceinline__ void split_store(float x, float y, float z, float w,
                                            __nv_bfloat16* ph, __nv_bfloat16* pl) {
    __nv_bfloat162 h01, h23, l01, l23;
    h01.x = __float2bfloat16(x); h01.y = __float2bfloat16(y);
    h23.x = __float2bfloat16(z); h23.y = __float2bfloat16(w);
    l01.x = __float2bfloat16(x - __bfloat162float(h01.x));
    l01.y = __float2bfloat16(y - __bfloat162float(h01.y));
    l23.x = __float2bfloat16(z - __bfloat162float(h23.x));
    l23.y = __float2bfloat16(w - __bfloat162float(h23.y));
    *(uint2*)ph = make_uint2(*(uint32_t*)&h01, *(uint32_t*)&h23);
    *(uint2*)pl = make_uint2(*(uint32_t*)&l01, *(uint32_t*)&l23);
}

// ---------------- fused build: preps + degree + scan + dinv + CSR fill ----------------
__global__ __launch_bounds__(BB)
void build_all(const float* __restrict__ X, const int* __restrict__ src,
               const int* __restrict__ dst,
               const float* __restrict__ W0, const float* __restrict__ W1,
               const float* __restrict__ W2,
               int n, int E, int nblocks) {
    __shared__ int s[BB];
    __shared__ int s2[NB_MAX];

    const int tid = threadIdx.x;
    const int b   = blockIdx.x;
    const int gi  = b * BB + tid;
    const int gsz = nblocks * BB;

    // ---- P0: W^T splits, X splits, zero cnt (all independent) ----
    for (int i = gi; i < 3 * D * D; i += gsz) {
        int l = i / (D * D);
        int r = i % (D * D);
        int nn = r >> 7, kk = r & 127;
        const float* W = (l == 0) ? W0 : ((l == 1) ? W1 : W2);
        float f = W[kk * D + nn];
        __nv_bfloat16 h = __float2bfloat16(f);
        g_wt_hi[i] = h;
        g_wt_lo[i] = __float2bfloat16(f - __bfloat162float(h));
    }
    for (int i = gi; i < n * (D / 4); i += gsz) {
        float4 v = *(const float4*)&X[(size_t)i * 4];
        split_store(v.x, v.y, v.z, v.w, &g_xh[(size_t)i * 4], &g_xl[(size_t)i * 4]);
    }
    if (gi < n) g_cnt[gi] = 0;
    grid_barrier(nblocks);

    // ---- P1: degree histogram ----
    for (int i = gi; i < E; i += gsz) atomicAdd(&g_cnt[__ldg(&dst[i])], 1);
    grid_barrier(nblocks);

    // ---- P2: block-local inclusive scan (Hillis-Steele) ----
    int v = (gi < n) ? g_cnt[gi] : 0;
    s[tid] = v;
    __syncthreads();
    #pragma unroll
    for (int off = 1; off < BB; off <<= 1) {
        int t = (tid >= off) ? s[tid - off] : 0;
        __syncthreads();
        s[tid] += t;
        __syncthreads();
    }
    int incl = s[tid];
    if (tid == BB - 1) g_blocksum[b] = incl;
    grid_barrier(nblocks);

    // ---- P3: block 0 scans block sums ----
    if (b == 0) {
        int u = (tid < nblocks) ? g_blocksum[tid] : 0;
        if (tid < NB_MAX) s2[tid] = u;
        __syncthreads();
        #pragma unroll
        for (int off = 1; off < NB_MAX; off <<= 1) {
            int t = (tid >= off && tid < NB_MAX) ? s2[tid - off] : 0;
            __syncthreads();
            if (tid < NB_MAX) s2[tid] += t;
            __syncthreads();
        }
        if (tid < nblocks) g_blockoff[tid] = s2[tid] - u;
        if (tid == nblocks - 1) g_rowptr[n] = s2[tid];
    }
    grid_barrier(nblocks);

    // ---- P4: rowptr / cursor / dinv ----
    if (gi < n) {
        int excl = incl - v + g_blockoff[b];
        g_rowptr[gi] = excl;
        g_cursor[gi] = excl;
        g_dinv[gi]   = rsqrtf((float)(v + 1));
    }
    grid_barrier(nblocks);

    // ---- P5: CSR fill ----
    for (int i = gi; i < E; i += gsz) {
        int d = __ldg(&dst[i]);
        int pos = atomicAdd(&g_cursor[d], 1);
        g_csr[pos] = __ldg(&src[i]);
    }
}

// ---------------- bf16x3 GEMM (mma.sync), bf16 inputs, M=64 tile ----------------
#define PITCH 68
#define A_ROWS 64
#define SM_A (A_ROWS * PITCH)
#define SM_B (128 * PITCH)
#define SM_TOTAL_B ((2 * SM_A + 2 * SM_B) * 4)   // 104448 bytes -> 2 CTAs/SM

__device__ __forceinline__ void mma16816(float* c, const uint32_t* a, const uint32_t* b) {
    asm volatile(
        "mma.sync.aligned.m16n8k16.row.col.f32.bf16.bf16.f32 "
        "{%0,%1,%2,%3}, {%4,%5,%6,%7}, {%8,%9}, {%0,%1,%2,%3};"
        : "+f"(c[0]), "+f"(c[1]), "+f"(c[2]), "+f"(c[3])
        : "r"(a[0]), "r"(a[1]), "r"(a[2]), "r"(a[3]), "r"(b[0]), "r"(b[1]));
}

__global__ __launch_bounds__(256, 2)
void gemm_mma(int layer, int nrows) {
    extern __shared__ uint32_t smem[];
    uint32_t* A_hi = smem;
    uint32_t* A_lo = A_hi + SM_A;
    uint32_t* B_hi = A_lo + SM_A;
    uint32_t* B_lo = B_hi + SM_B;

    const int tid = threadIdx.x;
    const int m0  = blockIdx.x * A_ROWS;
    const uint32_t sb = smem_u32(smem);

    #pragma unroll
    for (int i = 0; i < 4; i++) {
        int id  = tid + i * 256;
        int row = id >> 4;
        int q   = id & 15;
        int gr  = m0 + row;
        bool ok = gr < nrows;
        size_t gof = (size_t)gr * D + q * 8;
        uint32_t so = (row * PITCH + q * 4) * 4;
        cp_async16(sb + (uint32_t)((char*)A_hi - (char*)smem) + so, &g_xh[gof], ok);
        cp_async16(sb + (uint32_t)((char*)A_lo - (char*)smem) + so, &g_xl[gof], ok);
    }
    {
        const __nv_bfloat16* wh = &g_wt_hi[layer * D * D];
        const __nv_bfloat16* wl = &g_wt_lo[layer * D * D];
        #pragma unroll
        for (int i = 0; i < 8; i++) {
            int id = tid + i * 256;
            int nn = id >> 4;
            int q  = id & 15;
            size_t gof = (size_t)nn * D + q * 8;
            uint32_t so = (nn * PITCH + q * 4) * 4;
            cp_async16(sb + (uint32_t)((char*)B_hi - (char*)smem) + so, &wh[gof], true);
            cp_async16(sb + (uint32_t)((char*)B_lo - (char*)smem) + so, &wl[gof], true);
        }
    }
    CP_COMMIT();
    CP_WAIT_ALL();
    __syncthreads();

    const int wid  = tid >> 5;
    const int lane = tid & 31;
    const int g    = lane >> 2;
    const int tig  = lane & 3;
    const int wm   = (wid & 1) * 32;
    const int wn   = (wid >> 1) * 32;

    float acc[2][4][4];
    #pragma unroll
    for (int mt = 0; mt < 2; mt++)
        #pragma unroll
        for (int nt = 0; nt < 4; nt++)
            #pragma unroll
            for (int e = 0; e < 4; e++) acc[mt][nt][e] = 0.f;

    #pragma unroll
    for (int split = 0; split < 3; split++) {
        const uint32_t* Ap = (split == 2) ? A_lo : A_hi;
        const uint32_t* Bp = (split == 1) ? B_lo : B_hi;
        #pragma unroll
        for (int step = 0; step < 8; step++) {
            int kb = step * 8;
            uint32_t a[2][4], bfr[4][2];
            #pragma unroll
            for (int mt = 0; mt < 2; mt++) {
                int r = wm + mt * 16 + g;
                a[mt][0] = Ap[r * PITCH + kb + tig];
                a[mt][1] = Ap[(r + 8) * PITCH + kb + tig];
                a[mt][2] = Ap[r * PITCH + kb + tig + 4];
                a[mt][3] = Ap[(r + 8) * PITCH + kb + tig + 4];
            }
            #pragma unroll
            for (int nt = 0; nt < 4; nt++) {
                int c = wn + nt * 8 + g;
                bfr[nt][0] = Bp[c * PITCH + kb + tig];
                bfr[nt][1] = Bp[c * PITCH + kb + tig + 4];
            }
            #pragma unroll
            for (int mt = 0; mt < 2; mt++)
                #pragma unroll
                for (int nt = 0; nt < 4; nt++)
                    mma16816(acc[mt][nt], a[mt], bfr[nt]);
        }
    }

    #pragma unroll
    for (int mt = 0; mt < 2; mt++) {
        #pragma unroll
        for (int half = 0; half < 2; half++) {
            int row = m0 + wm + mt * 16 + g + half * 8;
            if (row >= nrows) continue;
            float dv = g_dinv[row];
            #pragma unroll
            for (int nt = 0; nt < 4; nt++) {
                float2 v;
                v.x = dv * acc[mt][nt][half * 2 + 0];
                v.y = dv * acc[mt][nt][half * 2 + 1];
                *(float2*)&g_buf[(size_t)row * D + wn + nt * 8 + tig * 2] = v;
            }
        }
    }
}

// ---------------- aggregate ----------------
// out[v] = relu(dinv[v]*(g[v] + sum g[nbr]) + b). Warp per node, edge loop unroll x4.
template <bool TO_GX>
__global__ __launch_bounds__(256)
void aggregate(const float* __restrict__ bias, float* __restrict__ outp, int n) {
    int w    = (blockIdx.x * blockDim.x + threadIdx.x) >> 5;
    int lane = threadIdx.x & 31;
    if (w >= n) return;

    int beg = g_rowptr[w];
    int end = g_rowptr[w + 1];
    size_t col = (size_t)lane * 4;

    float4 acc = *(const float4*)&g_buf[(size_t)w * D + col];   // self-loop

    int e = beg;
    for (; e + 4 <= end; e += 4) {
        int s0 = __ldg(&g_csr[e]);
        int s1 = __ldg(&g_csr[e + 1]);
        int s2 = __ldg(&g_csr[e + 2]);
        int s3 = __ldg(&g_csr[e + 3]);
        float4 v0 = *(const float4*)&g_buf[(size_t)s0 * D + col];
        float4 v1 = *(const float4*)&g_buf[(size_t)s1 * D + col];
        float4 v2 = *(const float4*)&g_buf[(size_t)s2 * D + col];
        float4 v3 = *(const float4*)&g_buf[(size_t)s3 * D + col];
        acc.x += (v0.x + v1.x) + (v2.x + v3.x);
        acc.y += (v0.y + v1.y) + (v2.y + v3.y);
        acc.z += (v0.z + v1.z) + (v2.z + v3.z);
        acc.w += (v0.w + v1.w) + (v2.w + v3.w);
    }
    for (; e < end; e++) {
        int s0 = __ldg(&g_csr[e]);
        float4 v0 = *(const float4*)&g_buf[(size_t)s0 * D + col];
        acc.x += v0.x; acc.y += v0.y; acc.z += v0.z; acc.w += v0.w;
    }

    float dv = g_dinv[w];
    float4 b = *(const float4*)&bias[col];
    float4 r;
    r.x = fmaxf(fmaf(dv, acc.x, b.x), 0.f);
    r.y = fmaxf(fmaf(dv, acc.y, b.y), 0.f);
    r.z = fmaxf(fmaf(dv, acc.z, b.z), 0.f);
    r.w = fmaxf(fmaf(dv, acc.w, b.w), 0.f);

    if (TO_GX) {
        size_t off = (size_t)w * D + col;
        split_store(r.x, r.y, r.z, r.w, &g_xh[off], &g_xl[off]);
    } else {
        *(float4*)&outp[(size_t)w * D + col] = r;
    }
}

// ---------------- launch ----------------
extern "C" void kernel_launch(void* const* d_in, const int* in_sizes, int n_in,
                              void* d_out, int out_size) {
    const float* node_fts = (const float*)d_in[0];
    const int*   edge     = (const int*)d_in[1];   // int32
    const float* W[3] = { (const float*)d_in[2], (const float*)d_in[4], (const float*)d_in[6] };
    const float* B[3] = { (const float*)d_in[3], (const float*)d_in[5], (const float*)d_in[7] };

    const int nrows = in_sizes[0] / D;
    const int E     = in_sizes[1] / 2;
    const int* src  = edge;
    const int* dst  = edge + E;

    static bool attr_done = false;
    if (!attr_done) {
        cudaFuncSetAttribute(gemm_mma, cudaFuncAttributeMaxDynamicSharedMemorySize, SM_TOTAL_B);
        attr_done = true;
    }

    const int nblocks = (nrows + BB - 1) / BB;   // 98 for n=100k; single wave on 148 SMs

    // one fused kernel: preps + degree + scan + dinv + CSR fill
    build_all<<<nblocks, BB>>>(node_fts, src, dst, W[0], W[1], W[2], nrows, E, nblocks);

    const int gemm_blocks = (nrows + A_ROWS - 1) / A_ROWS;
    const int agg_blocks  = (nrows * 32 + 255) / 256;

    // Layer 1
    gemm_mma<<<gemm_blocks, 256, SM_TOTAL_B>>>(0, nrows);
    aggregate<true><<<agg_blocks, 256>>>(B[0], nullptr, nrows);
    // Layer 2
    gemm_mma<<<gemm_blocks, 256, SM_TOTAL_B>>>(1, nrows);
    aggregate<true><<<agg_blocks, 256>>>(B[1], nullptr, nrows);
    // Layer 3
    gemm_mma<<<gemm_blocks, 256, SM_TOTAL_B>>>(2, nrows);
    aggregate<false><<<agg_blocks, 256>>>(B[2], (float*)d_out, nrows);
}

// round 11
// speedup vs baseline: 1.1769x; 1.1769x over previous
#include <cuda_runtime.h>
#include <cuda_bf16.h>
#include <cstdint>

#define N_MAX 100000
#define E_MAX 1700000
#define D 128
#define SCAN_B 1024
#define MAX_BLOCKS 128

// ---------------- scratch (static device globals) ----------------
__device__ __align__(16) float g_buf[N_MAX * D];            // g[u] = dinv[u]*(X@W)[u]
__device__ __align__(16) __nv_bfloat16 g_xh[N_MAX * D];     // activation hi split
__device__ __align__(16) __nv_bfloat16 g_xl[N_MAX * D];     // activation lo split
__device__ float g_dinv[N_MAX];
__device__ int   g_cnt[N_MAX];
__device__ int   g_rowptr[N_MAX + 1];
__device__ int   g_cursor[N_MAX];
__device__ int   g_blocksum[MAX_BLOCKS];
__device__ int   g_blockoff[MAX_BLOCKS];
__device__ int   g_csr[E_MAX];
__device__ __align__(16) __nv_bfloat16 g_wt_hi[3 * D * D];  // W^T hi split [l][n][k]
__device__ __align__(16) __nv_bfloat16 g_wt_lo[3 * D * D];  // W^T lo split

// ---------------- helpers ----------------
__device__ __forceinline__ uint32_t smem_u32(const void* p) {
    uint32_t a;
    asm("{ .reg .u64 t; cvta.to.shared.u64 t, %1; cvt.u32.u64 %0, t; }" : "=r"(a) : "l"(p));
    return a;
}
__device__ __forceinline__ void cp_async16(uint32_t saddr, const void* gptr, bool valid) {
    int sz = valid ? 16 : 0;
    asm volatile("cp.async.cg.shared.global [%0], [%1], 16, %2;"
                 :: "r"(saddr), "l"(gptr), "r"(sz));
}
#define CP_COMMIT()    asm volatile("cp.async.commit_group;")
#define CP_WAIT_ALL()  asm volatile("cp.async.wait_all;" ::: "memory")
#define CP_WAIT_1()    asm volatile("cp.async.wait_group 1;" ::: "memory")

__device__ __forceinline__ void split_store(float x, float y, float z, float w,
                                            __nv_bfloat16* ph, __nv_bfloat16* pl) {
    __nv_bfloat162 h01, h23, l01, l23;
    h01.x = __float2bfloat16(x); h01.y = __float2bfloat16(y);
    h23.x = __float2bfloat16(z); h23.y = __float2bfloat16(w);
    l01.x = __float2bfloat16(x - __bfloat162float(h01.x));
    l01.y = __float2bfloat16(y - __bfloat162float(h01.y));
    l23.x = __float2bfloat16(z - __bfloat162float(h23.x));
    l23.y = __float2bfloat16(w - __bfloat162float(h23.y));
    *(uint2*)ph = make_uint2(*(uint32_t*)&h01, *(uint32_t*)&h23);
    *(uint2*)pl = make_uint2(*(uint32_t*)&l01, *(uint32_t*)&l23);
}

// ---------------- degree histogram / scan / CSR (R9 chain) ----------------
__global__ void cnt_zero(int n) {
    int i = blockIdx.x * blockDim.x + threadIdx.x;
    if (i < n) g_cnt[i] = 0;
}
__global__ void cnt_count(const int* __restrict__ dst, int E) {
    int i = blockIdx.x * blockDim.x + threadIdx.x;
    if (i < E) atomicAdd(&g_cnt[__ldg(&dst[i])], 1);
}
__global__ void scanA(int n) {
    __shared__ int s[SCAN_B];
    int i = blockIdx.x * SCAN_B + threadIdx.x;
    s[threadIdx.x] = (i < n) ? g_cnt[i] : 0;
    __syncthreads();
    for (int off = SCAN_B / 2; off > 0; off >>= 1) {
        if (threadIdx.x < off) s[threadIdx.x] += s[threadIdx.x + off];
        __syncthreads();
    }
    if (threadIdx.x == 0) g_blocksum[blockIdx.x] = s[0];
}
__global__ void scanB(int nblocks, int n) {
    __shared__ int s[MAX_BLOCKS];
    int t = threadIdx.x;
    int v = (t < nblocks) ? g_blocksum[t] : 0;
    s[t] = v; __syncthreads();
    for (int off = 1; off < MAX_BLOCKS; off <<= 1) {
        int u = (t >= off) ? s[t - off] : 0;
        __syncthreads();
        s[t] += u;
        __syncthreads();
    }
    if (t < nblocks) g_blockoff[t] = s[t] - v;
    if (t == nblocks - 1) g_rowptr[n] = s[t];
}
__global__ void scanC(int n) {
    __shared__ int s[SCAN_B];
    int i = blockIdx.x * SCAN_B + threadIdx.x;
    int v = (i < n) ? g_cnt[i] : 0;
    s[threadIdx.x] = v;
    __syncthreads();
    for (int off = 1; off < SCAN_B; off <<= 1) {
        int t = (threadIdx.x >= off) ? s[threadIdx.x - off] : 0;
        __syncthreads();
        s[threadIdx.x] += t;
        __syncthreads();
    }
    if (i < n) {
        int excl = s[threadIdx.x] - v + g_blockoff[blockIdx.x];
        g_rowptr[i] = excl;
        g_cursor[i] = excl;
        g_dinv[i]   = rsqrtf((float)(v + 1));
    }
}
__global__ void fill_csr(const int* __restrict__ src, const int* __restrict__ dst, int E) {
    int i = blockIdx.x * blockDim.x + threadIdx.x;
    if (i < E) {
        int d = __ldg(&dst[i]);
        int pos = atomicAdd(&g_cursor[d], 1);
        g_csr[pos] = __ldg(&src[i]);
    }
}

// ---------------- once-per-call prep ----------------
__global__ void prep_wt(const float* __restrict__ W0, const float* __restrict__ W1,
                        const float* __restrict__ W2) {
    int idx = blockIdx.x * blockDim.x + threadIdx.x;
    if (idx >= 3 * D * D) return;
    int l = idx / (D * D);
    int r = idx % (D * D);
    int n = r >> 7, k = r & 127;
    const float* W = (l == 0) ? W0 : ((l == 1) ? W1 : W2);
    float f = W[k * D + n];
    __nv_bfloat16 h = __float2bfloat16(f);
    g_wt_hi[idx] = h;
    g_wt_lo[idx] = __float2bfloat16(f - __bfloat162float(h));
}

__global__ void prep_x(const float* __restrict__ X, int total4) {
    int i = blockIdx.x * blockDim.x + threadIdx.x;
    if (i >= total4) return;
    float4 v = *(const float4*)&X[(size_t)i * 4];
    split_store(v.x, v.y, v.z, v.w, &g_xh[(size_t)i * 4], &g_xl[(size_t)i * 4]);
}

// ---------------- persistent bf16x3 GEMM (mma.sync) ----------------
// g_buf = dinv .* (X @ W). Grid = 296 persistent CTAs, 256 thr = 8 warps (2m x 4n),
// warp tile 16x32. B (both splits) resident in smem; A tiles (32 rows) double-buffered.
#define PITCH 68
#define AR 32
#define SM_B (128 * PITCH)          // b32, per split
#define SM_A (AR * PITCH)           // b32, per split per buffer
#define SM_TOTAL_B ((2 * SM_B + 4 * SM_A) * 4)   // 104448 bytes -> 2 CTAs/SM
#define GEMM_GRID 296

__device__ __forceinline__ void mma16816(float* c, const uint32_t* a, const uint32_t* b) {
    asm volatile(
        "mma.sync.aligned.m16n8k16.row.col.f32.bf16.bf16.f32 "
        "{%0,%1,%2,%3}, {%4,%5,%6,%7}, {%8,%9}, {%0,%1,%2,%3};"
        : "+f"(c[0]), "+f"(c[1]), "+f"(c[2]), "+f"(c[3])
        : "r"(a[0]), "r"(a[1]), "r"(a[2]), "r"(a[3]), "r"(b[0]), "r"(b[1]));
}

__global__ __launch_bounds__(256, 2)
void gemm_mma(int layer, int nrows, int ntiles) {
    extern __shared__ uint32_t smem[];
    uint32_t* Bh = smem;
    uint32_t* Bl = Bh + SM_B;
    uint32_t* Ab = Bl + SM_B;       // [buf][hi|lo], each SM_A

    const int tid = threadIdx.x;
    const uint32_t sb  = smem_u32(smem);
    const uint32_t sBh = sb;
    const uint32_t sBl = sb + SM_B * 4;
    const uint32_t sA  = sb + 2 * SM_B * 4;

    // --- B resident load (both splits), one group ---
    {
        const __nv_bfloat16* wh = &g_wt_hi[layer * D * D];
        const __nv_bfloat16* wl = &g_wt_lo[layer * D * D];
        #pragma unroll
        for (int i = 0; i < 8; i++) {
            int id = tid + i * 256;         // 0..2047
            int n  = id >> 4;
            int q  = id & 15;
            size_t gof = (size_t)n * D + q * 8;
            uint32_t so = (n * PITCH + q * 4) * 4;
            cp_async16(sBh + so, &wh[gof], true);
            cp_async16(sBl + so, &wl[gof], true);
        }
    }
    CP_COMMIT();

    // --- A tile prefetch helper: AR rows x 128 cols bf16, hi+lo ---
    auto loadA = [&](int buf, int t) {
        int m0 = t * AR;
        uint32_t base = sA + (uint32_t)buf * (2 * SM_A * 4);
        #pragma unroll
        for (int i = 0; i < 2; i++) {
            int id  = tid + i * 256;        // 0..511 (AR*16 chunks per split)
            int row = id >> 4;
            int q   = id & 15;
            int gr  = m0 + row;
            bool ok = gr < nrows;
            size_t gof = (size_t)gr * D + q * 8;
            uint32_t so = (row * PITCH + q * 4) * 4;
            cp_async16(base + so, &g_xh[gof], ok);
            cp_async16(base + SM_A * 4 + so, &g_xl[gof], ok);
        }
    };

    const int t0     = blockIdx.x;
    const int stride = gridDim.x;
    if (t0 < ntiles) loadA(0, t0);
    CP_COMMIT();

    const int wid  = tid >> 5;
    const int lane = tid & 31;
    const int g    = lane >> 2;
    const int tig  = lane & 3;
    const int wm   = (wid & 1) * 16;        // M in {0,16}
    const int wn   = (wid >> 1) * 32;       // N in {0,32,64,96}

    int buf = 0;
    for (int t = t0; t < ntiles; t += stride) {
        int nxt = t + stride;
        if (nxt < ntiles) loadA(buf ^ 1, nxt);
        CP_COMMIT();
        CP_WAIT_1();                         // B + A(cur) complete; A(next) may fly
        __syncthreads();

        const uint32_t* Ah = Ab + buf * (2 * SM_A);
        const uint32_t* Al = Ah + SM_A;

        float acc[4][4];
        #pragma unroll
        for (int nt = 0; nt < 4; nt++)
            #pragma unroll
            for (int e = 0; e < 4; e++) acc[nt][e] = 0.f;

        #pragma unroll
        for (int split = 0; split < 3; split++) {
            const uint32_t* Ap = (split == 2) ? Al : Ah;
            const uint32_t* Bp = (split == 1) ? Bl : Bh;
            #pragma unroll
            for (int step = 0; step < 8; step++) {
                int kb = step * 8;
                int r  = wm + g;
                uint32_t a[4], b[4][2];
                a[0] = Ap[r * PITCH + kb + tig];
                a[1] = Ap[(r + 8) * PITCH + kb + tig];
                a[2] = Ap[r * PITCH + kb + tig + 4];
                a[3] = Ap[(r + 8) * PITCH + kb + tig + 4];
                #pragma unroll
                for (int nt = 0; nt < 4; nt++) {
                    int c = wn + nt * 8 + g;
                    b[nt][0] = Bp[c * PITCH + kb + tig];
                    b[nt][1] = Bp[c * PITCH + kb + tig + 4];
                }
                #pragma unroll
                for (int nt = 0; nt < 4; nt++)
                    mma16816(acc[nt], a, b[nt]);
            }
        }

        // epilogue: scale by dinv[row], store fp32
        int m0 = t * AR;
        #pragma unroll
        for (int half = 0; half < 2; half++) {
            int row = m0 + wm + g + half * 8;
            if (row < nrows) {
                float dv = g_dinv[row];
                #pragma unroll
                for (int nt = 0; nt < 4; nt++) {
                    float2 v;
                    v.x = dv * acc[nt][half * 2 + 0];
                    v.y = dv * acc[nt][half * 2 + 1];
                    *(float2*)&g_buf[(size_t)row * D + wn + nt * 8 + tig * 2] = v;
                }
            }
        }
        __syncthreads();                     // all reads of buf done before next overwrite
        buf ^= 1;
    }
    CP_WAIT_ALL();                           // drain any in-flight group before exit
}

// ---------------- aggregate ----------------
template <bool TO_GX>
__global__ __launch_bounds__(256)
void aggregate(const float* __restrict__ bias, float* __restrict__ outp, int n) {
    int w    = (blockIdx.x * blockDim.x + threadIdx.x) >> 5;
    int lane = threadIdx.x & 31;
    if (w >= n) return;

    int beg = g_rowptr[w];
    int end = g_rowptr[w + 1];
    size_t col = (size_t)lane * 4;

    float4 acc = *(const float4*)&g_buf[(size_t)w * D + col];   // self-loop

    int e = beg;
    for (; e + 4 <= end; e += 4) {
        int s0 = __ldg(&g_csr[e]);
        int s1 = __ldg(&g_csr[e + 1]);
        int s2 = __ldg(&g_csr[e + 2]);
        int s3 = __ldg(&g_csr[e + 3]);
        float4 v0 = *(const float4*)&g_buf[(size_t)s0 * D + col];
        float4 v1 = *(const float4*)&g_buf[(size_t)s1 * D + col];
        float4 v2 = *(const float4*)&g_buf[(size_t)s2 * D + col];
        float4 v3 = *(const float4*)&g_buf[(size_t)s3 * D + col];
        acc.x += (v0.x + v1.x) + (v2.x + v3.x);
        acc.y += (v0.y + v1.y) + (v2.y + v3.y);
        acc.z += (v0.z + v1.z) + (v2.z + v3.z);
        acc.w += (v0.w + v1.w) + (v2.w + v3.w);
    }
    for (; e < end; e++) {
        int s0 = __ldg(&g_csr[e]);
        float4 v0 = *(const float4*)&g_buf[(size_t)s0 * D + col];
        acc.x += v0.x; acc.y += v0.y; acc.z += v0.z; acc.w += v0.w;
    }

    float dv = g_dinv[w];
    float4 b = *(const float4*)&bias[col];
    float4 r;
    r.x = fmaxf(fmaf(dv, acc.x, b.x), 0.f);
    r.y = fmaxf(fmaf(dv, acc.y, b.y), 0.f);
    r.z = fmaxf(fmaf(dv, acc.z, b.z), 0.f);
    r.w = fmaxf(fmaf(dv, acc.w, b.w), 0.f);

    if (TO_GX) {
        size_t off = (size_t)w * D + col;
        split_store(r.x, r.y, r.z, r.w, &g_xh[off], &g_xl[off]);
    } else {
        *(float4*)&outp[(size_t)w * D + col] = r;
    }
}

// ---------------- launch ----------------
extern "C" void kernel_launch(void* const* d_in, const int* in_sizes, int n_in,
                              void* d_out, int out_size) {
    const float* node_fts = (const float*)d_in[0];
    const int*   edge     = (const int*)d_in[1];   // int32
    const float* W[3] = { (const float*)d_in[2], (const float*)d_in[4], (const float*)d_in[6] };
    const float* B[3] = { (const float*)d_in[3], (const float*)d_in[5], (const float*)d_in[7] };

    const int nrows = in_sizes[0] / D;
    const int E     = in_sizes[1] / 2;
    const int* src  = edge;
    const int* dst  = edge + E;

    static bool attr_done = false;
    if (!attr_done) {
        cudaFuncSetAttribute(gemm_mma, cudaFuncAttributeMaxDynamicSharedMemorySize, SM_TOTAL_B);
        attr_done = true;
    }

    const int scan_blocks = (nrows + SCAN_B - 1) / SCAN_B;

    // CSR build + dinv + W/X splits
    cnt_zero<<<(nrows + 255) / 256, 256>>>(nrows);
    cnt_count<<<(E + 255) / 256, 256>>>(dst, E);
    scanA<<<scan_blocks, SCAN_B>>>(nrows);
    scanB<<<1, MAX_BLOCKS>>>(scan_blocks, nrows);
    scanC<<<scan_blocks, SCAN_B>>>(nrows);
    fill_csr<<<(E + 255) / 256, 256>>>(src, dst, E);
    prep_wt<<<(3 * D * D + 255) / 256, 256>>>(W[0], W[1], W[2]);
    const int total4 = nrows * D / 4;
    prep_x<<<(total4 + 255) / 256, 256>>>(node_fts, total4);

    const int ntiles     = (nrows + AR - 1) / AR;
    const int agg_blocks = (nrows * 32 + 255) / 256;

    // Layer 1
    gemm_mma<<<GEMM_GRID, 256, SM_TOTAL_B>>>(0, nrows, ntiles);
    aggregate<true><<<agg_blocks, 256>>>(B[0], nullptr, nrows);
    // Layer 2
    gemm_mma<<<GEMM_GRID, 256, SM_TOTAL_B>>>(1, nrows, ntiles);
    aggregate<true><<<agg_blocks, 256>>>(B[1], nullptr, nrows);
    // Layer 3
    gemm_mma<<<GEMM_GRID, 256, SM_TOTAL_B>>>(2, nrows, ntiles);
    aggregate<false><<<agg_blocks, 256>>>(B[2], (float*)d_out, nrows);
}

// round 12
// speedup vs baseline: 1.2426x; 1.0558x over previous
#include <cuda_runtime.h>
#include <cuda_bf16.h>
#include <cstdint>

#define N_MAX 100000
#define E_MAX 1700000
#define D 128
#define SCAN_B 1024
#define MAX_BLOCKS 128

// ---------------- scratch (static device globals) ----------------
__device__ __align__(16) float g_buf[N_MAX * D];            // g[u] = dinv[u]*(X@W)[u]
__device__ __align__(16) __nv_bfloat16 g_xh[N_MAX * D];     // activation hi split
__device__ __align__(16) __nv_bfloat16 g_xl[N_MAX * D];     // activation lo split
__device__ float g_dinv[N_MAX];
__device__ int   g_cnt[N_MAX];
__device__ int   g_rowptr[N_MAX + 1];
__device__ int   g_cursor[N_MAX];
__device__ int   g_blocksum[MAX_BLOCKS];
__device__ int   g_blockoff[MAX_BLOCKS];
__device__ int   g_csr[E_MAX];
__device__ __align__(16) __nv_bfloat16 g_wt_hi[3 * D * D];  // W^T hi split [l][n][k]
__device__ __align__(16) __nv_bfloat16 g_wt_lo[3 * D * D];  // W^T lo split

// ---------------- helpers ----------------
__device__ __forceinline__ uint32_t smem_u32(const void* p) {
    uint32_t a;
    asm("{ .reg .u64 t; cvta.to.shared.u64 t, %1; cvt.u32.u64 %0, t; }" : "=r"(a) : "l"(p));
    return a;
}
__device__ __forceinline__ void cp_async16(uint32_t saddr, const void* gptr, bool valid) {
    int sz = valid ? 16 : 0;
    asm volatile("cp.async.cg.shared.global [%0], [%1], 16, %2;"
                 :: "r"(saddr), "l"(gptr), "r"(sz));
}
#define CP_COMMIT()    asm volatile("cp.async.commit_group;")
#define CP_WAIT_ALL()  asm volatile("cp.async.wait_all;" ::: "memory")
#define CP_WAIT_1()    asm volatile("cp.async.wait_group 1;" ::: "memory")

__device__ __forceinline__ void split_store(float x, float y, float z, float w,
                                            __nv_bfloat16* ph, __nv_bfloat16* pl) {
    __nv_bfloat162 h01, h23, l01, l23;
    h01.x = __float2bfloat16(x); h01.y = __float2bfloat16(y);
    h23.x = __float2bfloat16(z); h23.y = __float2bfloat16(w);
    l01.x = __float2bfloat16(x - __bfloat162float(h01.x));
    l01.y = __float2bfloat16(y - __bfloat162float(h01.y));
    l23.x = __float2bfloat16(z - __bfloat162float(h23.x));
    l23.y = __float2bfloat16(w - __bfloat162float(h23.y));
    *(uint2*)ph = make_uint2(*(uint32_t*)&h01, *(uint32_t*)&h23);
    *(uint2*)pl = make_uint2(*(uint32_t*)&l01, *(uint32_t*)&l23);
}

// ---------------- degree histogram / scan / CSR ----------------
__global__ void cnt_count(const int* __restrict__ dst, int E) {
    int i = blockIdx.x * blockDim.x + threadIdx.x;
    if (i < E) atomicAdd(&g_cnt[__ldg(&dst[i])], 1);
}
__global__ void scanA(int n) {
    __shared__ int s[SCAN_B];
    int i = blockIdx.x * SCAN_B + threadIdx.x;
    s[threadIdx.x] = (i < n) ? g_cnt[i] : 0;
    __syncthreads();
    for (int off = SCAN_B / 2; off > 0; off >>= 1) {
        if (threadIdx.x < off) s[threadIdx.x] += s[threadIdx.x + off];
        __syncthreads();
    }
    if (threadIdx.x == 0) g_blocksum[blockIdx.x] = s[0];
}
__global__ void scanB(int nblocks, int n) {
    __shared__ int s[MAX_BLOCKS];
    int t = threadIdx.x;
    int v = (t < nblocks) ? g_blocksum[t] : 0;
    s[t] = v; __syncthreads();
    for (int off = 1; off < MAX_BLOCKS; off <<= 1) {
        int u = (t >= off) ? s[t - off] : 0;
        __syncthreads();
        s[t] += u;
        __syncthreads();
    }
    if (t < nblocks) g_blockoff[t] = s[t] - v;
    if (t == nblocks - 1) g_rowptr[n] = s[t];
}
__global__ void scanC(int n) {
    __shared__ int s[SCAN_B];
    int i = blockIdx.x * SCAN_B + threadIdx.x;
    int v = (i < n) ? g_cnt[i] : 0;
    s[threadIdx.x] = v;
    __syncthreads();
    for (int off = 1; off < SCAN_B; off <<= 1) {
        int t = (threadIdx.x >= off) ? s[threadIdx.x - off] : 0;
        __syncthreads();
        s[threadIdx.x] += t;
        __syncthreads();
    }
    if (i < n) {
        int excl = s[threadIdx.x] - v + g_blockoff[blockIdx.x];
        g_rowptr[i] = excl;
        g_cursor[i] = excl;
        g_dinv[i]   = rsqrtf((float)(v + 1));
    }
}
__global__ void fill_csr(const int* __restrict__ src, const int* __restrict__ dst, int E) {
    int i = blockIdx.x * blockDim.x + threadIdx.x;
    if (i < E) {
        int d = __ldg(&dst[i]);
        int pos = atomicAdd(&g_cursor[d], 1);
        g_csr[pos] = __ldg(&src[i]);
    }
}

// ---------------- merged once-per-call prep: W splits + X splits + cnt zero ----------------
__global__ void prep_all(const float* __restrict__ X,
                         const float* __restrict__ W0, const float* __restrict__ W1,
                         const float* __restrict__ W2, int n) {
    int gi  = blockIdx.x * blockDim.x + threadIdx.x;
    int gsz = gridDim.x * blockDim.x;
    // X fp32 -> bf16 hi/lo (per float4)
    int total4 = n * (D / 4);
    for (int i = gi; i < total4; i += gsz) {
        float4 v = *(const float4*)&X[(size_t)i * 4];
        split_store(v.x, v.y, v.z, v.w, &g_xh[(size_t)i * 4], &g_xl[(size_t)i * 4]);
    }
    // W^T splits
    for (int i = gi; i < 3 * D * D; i += gsz) {
        int l = i / (D * D);
        int r = i % (D * D);
        int nn = r >> 7, kk = r & 127;
        const float* W = (l == 0) ? W0 : ((l == 1) ? W1 : W2);
        float f = W[kk * D + nn];
        __nv_bfloat16 h = __float2bfloat16(f);
        g_wt_hi[i] = h;
        g_wt_lo[i] = __float2bfloat16(f - __bfloat162float(h));
    }
    // zero degree counters
    if (gi < n) g_cnt[gi] = 0;
}

// ---------------- persistent bf16x3 GEMM, B fragments in registers ----------------
// g_buf = dinv .* (X @ W). Grid = 296 persistent CTAs, 256 thr = 8 warps.
// CTA tile: 32 rows x 128 cols. Warp tile: 32 x 16 (2m x 2n m16n8k16 tiles).
// B frags (both splits) loaded to regs once; A tiles double-buffered via cp.async.
#define PITCH 68
#define AR 32
#define SM_B (128 * PITCH)          // b32, per split
#define SM_A (AR * PITCH)           // b32, per split per buffer
#define SM_TOTAL_B ((2 * SM_B + 4 * SM_A) * 4)   // 104448 bytes -> 2 CTAs/SM
#define GEMM_GRID 296

__device__ __forceinline__ void mma16816(float* c, const uint32_t* a, const uint32_t* b) {
    asm volatile(
        "mma.sync.aligned.m16n8k16.row.col.f32.bf16.bf16.f32 "
        "{%0,%1,%2,%3}, {%4,%5,%6,%7}, {%8,%9}, {%0,%1,%2,%3};"
        : "+f"(c[0]), "+f"(c[1]), "+f"(c[2]), "+f"(c[3])
        : "r"(a[0]), "r"(a[1]), "r"(a[2]), "r"(a[3]), "r"(b[0]), "r"(b[1]));
}

__global__ __launch_bounds__(256, 2)
void gemm_mma(int layer, int nrows, int ntiles) {
    extern __shared__ uint32_t smem[];
    uint32_t* Bh = smem;
    uint32_t* Bl = Bh + SM_B;
    uint32_t* Ab = Bl + SM_B;       // [buf][hi|lo], each SM_A

    const int tid = threadIdx.x;
    const uint32_t sb  = smem_u32(smem);
    const uint32_t sBh = sb;
    const uint32_t sBl = sb + SM_B * 4;
    const uint32_t sA  = sb + 2 * SM_B * 4;

    // --- group0: B both splits -> smem ---
    {
        const __nv_bfloat16* wh = &g_wt_hi[layer * D * D];
        const __nv_bfloat16* wl = &g_wt_lo[layer * D * D];
        #pragma unroll
        for (int i = 0; i < 8; i++) {
            int id = tid + i * 256;
            int n  = id >> 4;
            int q  = id & 15;
            size_t gof = (size_t)n * D + q * 8;
            uint32_t so = (n * PITCH + q * 4) * 4;
            cp_async16(sBh + so, &wh[gof], true);
            cp_async16(sBl + so, &wl[gof], true);
        }
    }
    CP_COMMIT();

    auto loadA = [&](int buf, int t) {
        int m0 = t * AR;
        uint32_t base = sA + (uint32_t)buf * (2 * SM_A * 4);
        #pragma unroll
        for (int i = 0; i < 2; i++) {
            int id  = tid + i * 256;        // 0..511
            int row = id >> 4;
            int q   = id & 15;
            int gr  = m0 + row;
            bool ok = gr < nrows;
            size_t gof = (size_t)gr * D + q * 8;
            uint32_t so = (row * PITCH + q * 4) * 4;
            cp_async16(base + so, &g_xh[gof], ok);
            cp_async16(base + SM_A * 4 + so, &g_xl[gof], ok);
        }
    };

    const int t0     = blockIdx.x;
    const int stride = gridDim.x;
    if (t0 < ntiles) loadA(0, t0);      // group1
    CP_COMMIT();

    const int wid  = tid >> 5;
    const int lane = tid & 31;
    const int g    = lane >> 2;
    const int tig  = lane & 3;
    const int wn   = wid * 16;          // warp's 16-col slice

    // --- wait for B (group0), load B fragments into registers ---
    CP_WAIT_1();
    __syncthreads();

    uint32_t breg[2][8][2][2];          // [split hi/lo][step][nt][reg]
    #pragma unroll
    for (int sp = 0; sp < 2; sp++) {
        const uint32_t* Bp = sp ? Bl : Bh;
        #pragma unroll
        for (int step = 0; step < 8; step++) {
            #pragma unroll
            for (int nt = 0; nt < 2; nt++) {
                int c = wn + nt * 8 + g;
                breg[sp][step][nt][0] = Bp[c * PITCH + step * 8 + tig];
                breg[sp][step][nt][1] = Bp[c * PITCH + step * 8 + tig + 4];
            }
        }
    }

    int buf = 0;
    for (int t = t0; t < ntiles; t += stride) {
        int nxt = t + stride;
        if (nxt < ntiles) loadA(buf ^ 1, nxt);
        CP_COMMIT();
        CP_WAIT_1();                     // A(cur) done; A(next) may fly
        __syncthreads();

        const uint32_t* Ah = Ab + buf * (2 * SM_A);
        const uint32_t* Al = Ah + SM_A;

        float acc[2][2][4];              // [mt][nt][4]
        #pragma unroll
        for (int mt = 0; mt < 2; mt++)
            #pragma unroll
            for (int nt = 0; nt < 2; nt++)
                #pragma unroll
                for (int e = 0; e < 4; e++) acc[mt][nt][e] = 0.f;

        #pragma unroll
        for (int split = 0; split < 3; split++) {
            const uint32_t* Ap = (split == 2) ? Al : Ah;
            const int bsp = (split == 1) ? 1 : 0;
            #pragma unroll
            for (int step = 0; step < 8; step++) {
                int kb = step * 8;
                uint32_t a[2][4];
                #pragma unroll
                for (int mt = 0; mt < 2; mt++) {
                    int r = mt * 16 + g;
                    a[mt][0] = Ap[r * PITCH + kb + tig];
                    a[mt][1] = Ap[(r + 8) * PITCH + kb + tig];
                    a[mt][2] = Ap[r * PITCH + kb + tig + 4];
                    a[mt][3] = Ap[(r + 8) * PITCH + kb + tig + 4];
                }
                #pragma unroll
                for (int mt = 0; mt < 2; mt++)
                    #pragma unroll
                    for (int nt = 0; nt < 2; nt++)
                        mma16816(acc[mt][nt], a[mt], breg[bsp][step][nt]);
            }
        }

        // epilogue: scale by dinv[row], store fp32
        int m0 = t * AR;
        #pragma unroll
        for (int mt = 0; mt < 2; mt++) {
            #pragma unroll
            for (int half = 0; half < 2; half++) {
                int row = m0 + mt * 16 + g + half * 8;
                if (row < nrows) {
                    float dv = g_dinv[row];
                    #pragma unroll
                    for (int nt = 0; nt < 2; nt++) {
                        float2 v;
                        v.x = dv * acc[mt][nt][half * 2 + 0];
                        v.y = dv * acc[mt][nt][half * 2 + 1];
                        *(float2*)&g_buf[(size_t)row * D + wn + nt * 8 + tig * 2] = v;
                    }
                }
            }
        }
        __syncthreads();
        buf ^= 1;
    }
    CP_WAIT_ALL();
}

// ---------------- aggregate ----------------
template <bool TO_GX>
__global__ __launch_bounds__(256)
void aggregate(const float* __restrict__ bias, float* __restrict__ outp, int n) {
    int w    = (blockIdx.x * blockDim.x + threadIdx.x) >> 5;
    int lane = threadIdx.x & 31;
    if (w >= n) return;

    int beg = g_rowptr[w];
    int end = g_rowptr[w + 1];
    size_t col = (size_t)lane * 4;

    float4 acc = *(const float4*)&g_buf[(size_t)w * D + col];   // self-loop

    int e = beg;
    for (; e + 4 <= end; e += 4) {
        int s0 = __ldg(&g_csr[e]);
        int s1 = __ldg(&g_csr[e + 1]);
        int s2 = __ldg(&g_csr[e + 2]);
        int s3 = __ldg(&g_csr[e + 3]);
        float4 v0 = *(const float4*)&g_buf[(size_t)s0 * D + col];
        float4 v1 = *(const float4*)&g_buf[(size_t)s1 * D + col];
        float4 v2 = *(const float4*)&g_buf[(size_t)s2 * D + col];
        float4 v3 = *(const float4*)&g_buf[(size_t)s3 * D + col];
        acc.x += (v0.x + v1.x) + (v2.x + v3.x);
        acc.y += (v0.y + v1.y) + (v2.y + v3.y);
        acc.z += (v0.z + v1.z) + (v2.z + v3.z);
        acc.w += (v0.w + v1.w) + (v2.w + v3.w);
    }
    for (; e < end; e++) {
        int s0 = __ldg(&g_csr[e]);
        float4 v0 = *(const float4*)&g_buf[(size_t)s0 * D + col];
        acc.x += v0.x; acc.y += v0.y; acc.z += v0.z; acc.w += v0.w;
    }

    float dv = g_dinv[w];
    float4 b = *(const float4*)&bias[col];
    float4 r;
    r.x = fmaxf(fmaf(dv, acc.x, b.x), 0.f);
    r.y = fmaxf(fmaf(dv, acc.y, b.y), 0.f);
    r.z = fmaxf(fmaf(dv, acc.z, b.z), 0.f);
    r.w = fmaxf(fmaf(dv, acc.w, b.w), 0.f);

    if (TO_GX) {
        size_t off = (size_t)w * D + col;
        split_store(r.x, r.y, r.z, r.w, &g_xh[off], &g_xl[off]);
    } else {
        *(float4*)&outp[(size_t)w * D + col] = r;
    }
}

// ---------------- launch ----------------
extern "C" void kernel_launch(void* const* d_in, const int* in_sizes, int n_in,
                              void* d_out, int out_size) {
    const float* node_fts = (const float*)d_in[0];
    const int*   edge     = (const int*)d_in[1];   // int32
    const float* W[3] = { (const float*)d_in[2], (const float*)d_in[4], (const float*)d_in[6] };
    const float* B[3] = { (const float*)d_in[3], (const float*)d_in[5], (const float*)d_in[7] };

    const int nrows = in_sizes[0] / D;
    const int E     = in_sizes[1] / 2;
    const int* src  = edge;
    const int* dst  = edge + E;

    static bool attr_done = false;
    if (!attr_done) {
        cudaFuncSetAttribute(gemm_mma, cudaFuncAttributeMaxDynamicSharedMemorySize, SM_TOTAL_B);
        attr_done = true;
    }

    const int scan_blocks = (nrows + SCAN_B - 1) / SCAN_B;

    // merged prep (X/W splits + cnt zero), then degree/scan/CSR
    prep_all<<<(nrows * (D / 4) + 255) / 256, 256>>>(node_fts, W[0], W[1], W[2], nrows);
    cnt_count<<<(E + 255) / 256, 256>>>(dst, E);
    scanA<<<scan_blocks, SCAN_B>>>(nrows);
    scanB<<<1, MAX_BLOCKS>>>(scan_blocks, nrows);
    scanC<<<scan_blocks, SCAN_B>>>(nrows);
    fill_csr<<<(E + 255) / 256, 256>>>(src, dst, E);

    const int ntiles     = (nrows + AR - 1) / AR;
    const int agg_blocks = (nrows * 32 + 255) / 256;

    // Layer 1
    gemm_mma<<<GEMM_GRID, 256, SM_TOTAL_B>>>(0, nrows, ntiles);
    aggregate<true><<<agg_blocks, 256>>>(B[0], nullptr, nrows);
    // Layer 2
    gemm_mma<<<GEMM_GRID, 256, SM_TOTAL_B>>>(1, nrows, ntiles);
    aggregate<true><<<agg_blocks, 256>>>(B[1], nullptr, nrows);
    // Layer 3
    gemm_mma<<<GEMM_GRID, 256, SM_TOTAL_B>>>(2, nrows, ntiles);
    aggregate<false><<<agg_blocks, 256>>>(B[2], (float*)d_out, nrows);
}

// round 13
// speedup vs baseline: 1.2878x; 1.0364x over previous
#include <cuda_runtime.h>
#include <cuda_bf16.h>
#include <cstdint>

#define N_MAX 100000
#define E_MAX 1700000
#define D 128
#define SCAN_B 1024
#define MAX_BLOCKS 128

// ---------------- scratch (static device globals) ----------------
__device__ __align__(16) float g_buf[N_MAX * D];            // g[u] = dinv[u]*(X@W)[u]
__device__ __align__(16) __nv_bfloat16 g_xh[N_MAX * D];     // activation hi split
__device__ __align__(16) __nv_bfloat16 g_xl[N_MAX * D];     // activation lo split
__device__ float g_dinv[N_MAX];
__device__ int   g_cnt[N_MAX];
__device__ int   g_rowptr[N_MAX + 1];
__device__ int   g_cursor[N_MAX];
__device__ int   g_blocksum[MAX_BLOCKS];
__device__ int   g_blockoff[MAX_BLOCKS];
__device__ int   g_csr[E_MAX];
__device__ __align__(16) __nv_bfloat16 g_wt_hi[3 * D * D];  // W^T hi split [l][n][k]
__device__ __align__(16) __nv_bfloat16 g_wt_lo[3 * D * D];  // W^T lo split

// ---------------- helpers ----------------
__device__ __forceinline__ uint32_t smem_u32(const void* p) {
    uint32_t a;
    asm("{ .reg .u64 t; cvta.to.shared.u64 t, %1; cvt.u32.u64 %0, t; }" : "=r"(a) : "l"(p));
    return a;
}
__device__ __forceinline__ void cp_async16(uint32_t saddr, const void* gptr, bool valid) {
    int sz = valid ? 16 : 0;     // src-size 0 -> 16B zero-fill
    asm volatile("cp.async.cg.shared.global [%0], [%1], 16, %2;"
                 :: "r"(saddr), "l"(gptr), "r"(sz));
}
#define CP_COMMIT()    asm volatile("cp.async.commit_group;")
#define CP_WAIT_ALL()  asm volatile("cp.async.wait_all;" ::: "memory")
#define CP_WAIT_1()    asm volatile("cp.async.wait_group 1;" ::: "memory")

__device__ __forceinline__ void ldsm_x4(uint32_t* r, uint32_t saddr) {
    asm volatile("ldmatrix.sync.aligned.m8n8.x4.shared.b16 {%0,%1,%2,%3}, [%4];"
                 : "=r"(r[0]), "=r"(r[1]), "=r"(r[2]), "=r"(r[3]) : "r"(saddr));
}

__device__ __forceinline__ void split_store(float x, float y, float z, float w,
                                            __nv_bfloat16* ph, __nv_bfloat16* pl) {
    __nv_bfloat162 h01, h23, l01, l23;
    h01.x = __float2bfloat16(x); h01.y = __float2bfloat16(y);
    h23.x = __float2bfloat16(z); h23.y = __float2bfloat16(w);
    l01.x = __float2bfloat16(x - __bfloat162float(h01.x));
    l01.y = __float2bfloat16(y - __bfloat162float(h01.y));
    l23.x = __float2bfloat16(z - __bfloat162float(h23.x));
    l23.y = __float2bfloat16(w - __bfloat162float(h23.y));
    *(uint2*)ph = make_uint2(*(uint32_t*)&h01, *(uint32_t*)&h23);
    *(uint2*)pl = make_uint2(*(uint32_t*)&l01, *(uint32_t*)&l23);
}

// ---------------- degree histogram / scan / CSR ----------------
__global__ void cnt_count(const int* __restrict__ dst, int E) {
    int i = blockIdx.x * blockDim.x + threadIdx.x;
    if (i < E) atomicAdd(&g_cnt[__ldg(&dst[i])], 1);
}
__global__ void scanA(int n) {
    __shared__ int s[SCAN_B];
    int i = blockIdx.x * SCAN_B + threadIdx.x;
    s[threadIdx.x] = (i < n) ? g_cnt[i] : 0;
    __syncthreads();
    for (int off = SCAN_B / 2; off > 0; off >>= 1) {
        if (threadIdx.x < off) s[threadIdx.x] += s[threadIdx.x + off];
        __syncthreads();
    }
    if (threadIdx.x == 0) g_blocksum[blockIdx.x] = s[0];
}
__global__ void scanB(int nblocks, int n) {
    __shared__ int s[MAX_BLOCKS];
    int t = threadIdx.x;
    int v = (t < nblocks) ? g_blocksum[t] : 0;
    s[t] = v; __syncthreads();
    for (int off = 1; off < MAX_BLOCKS; off <<= 1) {
        int u = (t >= off) ? s[t - off] : 0;
        __syncthreads();
        s[t] += u;
        __syncthreads();
    }
    if (t < nblocks) g_blockoff[t] = s[t] - v;
    if (t == nblocks - 1) g_rowptr[n] = s[t];
}
__global__ void scanC(int n) {
    __shared__ int s[SCAN_B];
    int i = blockIdx.x * SCAN_B + threadIdx.x;
    int v = (i < n) ? g_cnt[i] : 0;
    s[threadIdx.x] = v;
    __syncthreads();
    for (int off = 1; off < SCAN_B; off <<= 1) {
        int t = (threadIdx.x >= off) ? s[threadIdx.x - off] : 0;
        __syncthreads();
        s[threadIdx.x] += t;
        __syncthreads();
    }
    if (i < n) {
        int excl = s[threadIdx.x] - v + g_blockoff[blockIdx.x];
        g_rowptr[i] = excl;
        g_cursor[i] = excl;
        g_dinv[i]   = rsqrtf((float)(v + 1));
    }
}
__global__ void fill_csr(const int* __restrict__ src, const int* __restrict__ dst, int E) {
    int i = blockIdx.x * blockDim.x + threadIdx.x;
    if (i < E) {
        int d = __ldg(&dst[i]);
        int pos = atomicAdd(&g_cursor[d], 1);
        g_csr[pos] = __ldg(&src[i]);
    }
}

// ---------------- merged prep: W splits + X splits + cnt zero ----------------
__global__ void prep_all(const float* __restrict__ X,
                         const float* __restrict__ W0, const float* __restrict__ W1,
                         const float* __restrict__ W2, int n) {
    int gi  = blockIdx.x * blockDim.x + threadIdx.x;
    int gsz = gridDim.x * blockDim.x;
    int total4 = n * (D / 4);
    for (int i = gi; i < total4; i += gsz) {
        float4 v = *(const float4*)&X[(size_t)i * 4];
        split_store(v.x, v.y, v.z, v.w, &g_xh[(size_t)i * 4], &g_xl[(size_t)i * 4]);
    }
    for (int i = gi; i < 3 * D * D; i += gsz) {
        int l = i / (D * D);
        int r = i % (D * D);
        int nn = r >> 7, kk = r & 127;
        const float* W = (l == 0) ? W0 : ((l == 1) ? W1 : W2);
        float f = W[kk * D + nn];
        __nv_bfloat16 h = __float2bfloat16(f);
        g_wt_hi[i] = h;
        g_wt_lo[i] = __float2bfloat16(f - __bfloat162float(h));
    }
    if (gi < n) g_cnt[gi] = 0;
}

// ---------------- persistent bf16x3 GEMM: ldmatrix + split-fused loop ----------------
// g_buf = dinv .* (X @ W). Grid = 296 persistent CTAs, 256 thr = 8 warps.
// CTA tile: 32 rows x 128 cols. Warp tile: 32 x 16 (2m x 2n m16n8k16 tiles).
// B frags (both splits) in registers; A tiles double-buffered; A frags via ldmatrix.x4.
#define PITCH 68
#define AR 32
#define SM_B (128 * PITCH)
#define SM_A (AR * PITCH)
#define SM_TOTAL_B ((2 * SM_B + 4 * SM_A) * 4)   // 104448 bytes -> 2 CTAs/SM
#define GEMM_GRID 296

__device__ __forceinline__ void mma16816(float* c, const uint32_t* a, const uint32_t* b) {
    asm volatile(
        "mma.sync.aligned.m16n8k16.row.col.f32.bf16.bf16.f32 "
        "{%0,%1,%2,%3}, {%4,%5,%6,%7}, {%8,%9}, {%0,%1,%2,%3};"
        : "+f"(c[0]), "+f"(c[1]), "+f"(c[2]), "+f"(c[3])
        : "r"(a[0]), "r"(a[1]), "r"(a[2]), "r"(a[3]), "r"(b[0]), "r"(b[1]));
}

__global__ __launch_bounds__(256, 2)
void gemm_mma(int layer, int nrows, int ntiles) {
    extern __shared__ uint32_t smem[];
    uint32_t* Bh = smem;
    uint32_t* Bl = Bh + SM_B;

    const int tid = threadIdx.x;
    const uint32_t sb  = smem_u32(smem);
    const uint32_t sBh = sb;
    const uint32_t sBl = sb + SM_B * 4;
    const uint32_t sA  = sb + 2 * SM_B * 4;

    // --- group0: B both splits -> smem ---
    {
        const __nv_bfloat16* wh = &g_wt_hi[layer * D * D];
        const __nv_bfloat16* wl = &g_wt_lo[layer * D * D];
        #pragma unroll
        for (int i = 0; i < 8; i++) {
            int id = tid + i * 256;
            int n  = id >> 4;
            int q  = id & 15;
            size_t gof = (size_t)n * D + q * 8;
            uint32_t so = (n * PITCH + q * 4) * 4;
            cp_async16(sBh + so, &wh[gof], true);
            cp_async16(sBl + so, &wl[gof], true);
        }
    }
    CP_COMMIT();

    auto loadA = [&](int buf, int t) {
        int m0 = t * AR;
        uint32_t base = sA + (uint32_t)buf * (2 * SM_A * 4);
        #pragma unroll
        for (int i = 0; i < 2; i++) {
            int id  = tid + i * 256;
            int row = id >> 4;
            int q   = id & 15;
            int gr  = m0 + row;
            bool ok = gr < nrows;
            size_t gof = (size_t)gr * D + q * 8;
            uint32_t so = (row * PITCH + q * 4) * 4;
            cp_async16(base + so, &g_xh[gof], ok);
            cp_async16(base + SM_A * 4 + so, &g_xl[gof], ok);
        }
    };

    const int t0     = blockIdx.x;
    const int stride = gridDim.x;
    if (t0 < ntiles) loadA(0, t0);      // group1
    CP_COMMIT();

    const int wid  = tid >> 5;
    const int lane = tid & 31;
    const int g    = lane >> 2;
    const int tig  = lane & 3;
    const int wn   = wid * 16;

    // ldmatrix per-lane offset: matrix m = lane/8, row-in = lane%8
    // row = (m&1)*8 + rowin (+ mt*16), k b32 = (m>>1)*4 (+ step*8)
    const int lm_m   = lane >> 3;
    const int lm_row = ((lm_m & 1) << 3) + (lane & 7);
    const int lm_kc  = (lm_m >> 1) << 2;
    const uint32_t lm_off = (uint32_t)(lm_row * PITCH + lm_kc) * 4;

    // --- wait for B (group0), load B fragments into registers ---
    CP_WAIT_1();
    __syncthreads();

    uint32_t breg[2][8][2][2];          // [split][step][nt][reg]
    #pragma unroll
    for (int sp = 0; sp < 2; sp++) {
        const uint32_t* Bp = sp ? Bl : Bh;
        #pragma unroll
        for (int step = 0; step < 8; step++) {
            #pragma unroll
            for (int nt = 0; nt < 2; nt++) {
                int c = wn + nt * 8 + g;
                breg[sp][step][nt][0] = Bp[c * PITCH + step * 8 + tig];
                breg[sp][step][nt][1] = Bp[c * PITCH + step * 8 + tig + 4];
            }
        }
    }

    int buf = 0;
    for (int t = t0; t < ntiles; t += stride) {
        int nxt = t + stride;
        if (nxt < ntiles) loadA(buf ^ 1, nxt);
        CP_COMMIT();
        CP_WAIT_1();
        __syncthreads();

        const uint32_t aHi = sA + (uint32_t)buf * (2 * SM_A * 4) + lm_off;
        const uint32_t aLo = aHi + SM_A * 4;

        float acc[2][2][4];
        #pragma unroll
        for (int mt = 0; mt < 2; mt++)
            #pragma unroll
            for (int nt = 0; nt < 2; nt++)
                #pragma unroll
                for (int e = 0; e < 4; e++) acc[mt][nt][e] = 0.f;

        #pragma unroll
        for (int step = 0; step < 8; step++) {
            const uint32_t koff = (uint32_t)(step * 8) * 4;
            uint32_t ah[2][4], al[2][4];
            #pragma unroll
            for (int mt = 0; mt < 2; mt++)
                ldsm_x4(ah[mt], aHi + (uint32_t)(mt * 16 * PITCH) * 4 + koff);
            #pragma unroll
            for (int mt = 0; mt < 2; mt++)
                ldsm_x4(al[mt], aLo + (uint32_t)(mt * 16 * PITCH) * 4 + koff);
            #pragma unroll
            for (int mt = 0; mt < 2; mt++) {
                #pragma unroll
                for (int nt = 0; nt < 2; nt++) {
                    mma16816(acc[mt][nt], ah[mt], breg[0][step][nt]);  // Ah*Bh
                    mma16816(acc[mt][nt], ah[mt], breg[1][step][nt]);  // Ah*Bl
                    mma16816(acc[mt][nt], al[mt], breg[0][step][nt]);  // Al*Bh
                }
            }
        }

        // epilogue: scale by dinv[row], store fp32
        int m0 = t * AR;
        #pragma unroll
        for (int mt = 0; mt < 2; mt++) {
            #pragma unroll
            for (int half = 0; half < 2; half++) {
                int row = m0 + mt * 16 + g + half * 8;
                if (row < nrows) {
                    float dv = g_dinv[row];
                    #pragma unroll
                    for (int nt = 0; nt < 2; nt++) {
                        float2 v;
                        v.x = dv * acc[mt][nt][half * 2 + 0];
                        v.y = dv * acc[mt][nt][half * 2 + 1];
                        *(float2*)&g_buf[(size_t)row * D + wn + nt * 8 + tig * 2] = v;
                    }
                }
            }
        }
        __syncthreads();
        buf ^= 1;
    }
    CP_WAIT_ALL();
}

// ---------------- aggregate ----------------
template <bool TO_GX>
__global__ __launch_bounds__(256)
void aggregate(const float* __restrict__ bias, float* __restrict__ outp, int n) {
    int w    = (blockIdx.x * blockDim.x + threadIdx.x) >> 5;
    int lane = threadIdx.x & 31;
    if (w >= n) return;

    int beg = g_rowptr[w];
    int end = g_rowptr[w + 1];
    size_t col = (size_t)lane * 4;

    float4 acc = *(const float4*)&g_buf[(size_t)w * D + col];   // self-loop

    int e = beg;
    for (; e + 4 <= end; e += 4) {
        int s0 = __ldg(&g_csr[e]);
        int s1 = __ldg(&g_csr[e + 1]);
        int s2 = __ldg(&g_csr[e + 2]);
        int s3 = __ldg(&g_csr[e + 3]);
        float4 v0 = *(const float4*)&g_buf[(size_t)s0 * D + col];
        float4 v1 = *(const float4*)&g_buf[(size_t)s1 * D + col];
        float4 v2 = *(const float4*)&g_buf[(size_t)s2 * D + col];
        float4 v3 = *(const float4*)&g_buf[(size_t)s3 * D + col];
        acc.x += (v0.x + v1.x) + (v2.x + v3.x);
        acc.y += (v0.y + v1.y) + (v2.y + v3.y);
        acc.z += (v0.z + v1.z) + (v2.z + v3.z);
        acc.w += (v0.w + v1.w) + (v2.w + v3.w);
    }
    for (; e < end; e++) {
        int s0 = __ldg(&g_csr[e]);
        float4 v0 = *(const float4*)&g_buf[(size_t)s0 * D + col];
        acc.x += v0.x; acc.y += v0.y; acc.z += v0.z; acc.w += v0.w;
    }

    float dv = g_dinv[w];
    float4 b = *(const float4*)&bias[col];
    float4 r;
    r.x = fmaxf(fmaf(dv, acc.x, b.x), 0.f);
    r.y = fmaxf(fmaf(dv, acc.y, b.y), 0.f);
    r.z = fmaxf(fmaf(dv, acc.z, b.z), 0.f);
    r.w = fmaxf(fmaf(dv, acc.w, b.w), 0.f);

    if (TO_GX) {
        size_t off = (size_t)w * D + col;
        split_store(r.x, r.y, r.z, r.w, &g_xh[off], &g_xl[off]);
    } else {
        *(float4*)&outp[(size_t)w * D + col] = r;
    }
}

// ---------------- launch ----------------
extern "C" void kernel_launch(void* const* d_in, const int* in_sizes, int n_in,
                              void* d_out, int out_size) {
    const float* node_fts = (const float*)d_in[0];
    const int*   edge     = (const int*)d_in[1];   // int32
    const float* W[3] = { (const float*)d_in[2], (const float*)d_in[4], (const float*)d_in[6] };
    const float* B[3] = { (const float*)d_in[3], (const float*)d_in[5], (const float*)d_in[7] };

    const int nrows = in_sizes[0] / D;
    const int E     = in_sizes[1] / 2;
    const int* src  = edge;
    const int* dst  = edge + E;

    static bool attr_done = false;
    if (!attr_done) {
        cudaFuncSetAttribute(gemm_mma, cudaFuncAttributeMaxDynamicSharedMemorySize, SM_TOTAL_B);
        attr_done = true;
    }

    const int scan_blocks = (nrows + SCAN_B - 1) / SCAN_B;

    prep_all<<<(nrows * (D / 4) + 255) / 256, 256>>>(node_fts, W[0], W[1], W[2], nrows);
    cnt_count<<<(E + 255) / 256, 256>>>(dst, E);
    scanA<<<scan_blocks, SCAN_B>>>(nrows);
    scanB<<<1, MAX_BLOCKS>>>(scan_blocks, nrows);
    scanC<<<scan_blocks, SCAN_B>>>(nrows);
    fill_csr<<<(E + 255) / 256, 256>>>(src, dst, E);

    const int ntiles     = (nrows + AR - 1) / AR;
    const int agg_blocks = (nrows * 32 + 255) / 256;

    // Layer 1
    gemm_mma<<<GEMM_GRID, 256, SM_TOTAL_B>>>(0, nrows, ntiles);
    aggregate<true><<<agg_blocks, 256>>>(B[0], nullptr, nrows);
    // Layer 2
    gemm_mma<<<GEMM_GRID, 256, SM_TOTAL_B>>>(1, nrows, ntiles);
    aggregate<true><<<agg_blocks, 256>>>(B[1], nullptr, nrows);
    // Layer 3
    gemm_mma<<<GEMM_GRID, 256, SM_TOTAL_B>>>(2, nrows, ntiles);
    aggregate<false><<<agg_blocks, 256>>>(B[2], (float*)d_out, nrows);
}

// round 14
// speedup vs baseline: 1.3040x; 1.0126x over previous
#include <cuda_runtime.h>
#include <cuda_bf16.h>
#include <cstdint>

#define N_MAX 100000
#define E_MAX 1700000
#define D 128
#define BB 1024
#define NB_MAX 128      // >= ceil(N_MAX/BB) = 98

// ---------------- scratch (static device globals) ----------------
__device__ __align__(16) float g_buf[N_MAX * D];            // g[u] = dinv[u]*(X@W)[u]
__device__ __align__(16) __nv_bfloat16 g_xh[N_MAX * D];     // activation hi split
__device__ __align__(16) __nv_bfloat16 g_xl[N_MAX * D];     // activation lo split
__device__ float g_dinv[N_MAX];
__device__ int   g_cnt[N_MAX];                              // ZERO on entry (see fill_csr)
__device__ int   g_rowptr[N_MAX + 1];
__device__ int   g_cursor[N_MAX];
__device__ int   g_blocksum[NB_MAX];
__device__ int   g_blockoff[NB_MAX];
__device__ int   g_csr[E_MAX];
__device__ __align__(16) __nv_bfloat16 g_wt_hi[3 * D * D];  // W^T hi split [l][n][k]
__device__ __align__(16) __nv_bfloat16 g_wt_lo[3 * D * D];  // W^T lo split
__device__ unsigned g_bar_cnt = 0;
__device__ unsigned g_bar_gen = 0;

// ---------------- helpers ----------------
__device__ __forceinline__ uint32_t smem_u32(const void* p) {
    uint32_t a;
    asm("{ .reg .u64 t; cvta.to.shared.u64 t, %1; cvt.u32.u64 %0, t; }" : "=r"(a) : "l"(p));
    return a;
}
__device__ __forceinline__ void cp_async16(uint32_t saddr, const void* gptr, bool valid) {
    int sz = valid ? 16 : 0;
    asm volatile("cp.async.cg.shared.global [%0], [%1], 16, %2;"
                 :: "r"(saddr), "l"(gptr), "r"(sz));
}
#define CP_COMMIT()    asm volatile("cp.async.commit_group;")
#define CP_WAIT_ALL()  asm volatile("cp.async.wait_all;" ::: "memory")
#define CP_WAIT_1()    asm volatile("cp.async.wait_group 1;" ::: "memory")

__device__ __forceinline__ void ldsm_x4(uint32_t* r, uint32_t saddr) {
    asm volatile("ldmatrix.sync.aligned.m8n8.x4.shared.b16 {%0,%1,%2,%3}, [%4];"
                 : "=r"(r[0]), "=r"(r[1]), "=r"(r[2]), "=r"(r[3]) : "r"(saddr));
}

__device__ __forceinline__ void split_store(float x, float y, float z, float w,
                                            __nv_bfloat16* ph, __nv_bfloat16* pl) {
    __nv_bfloat162 h01, h23, l01, l23;
    h01.x = __float2bfloat16(x); h01.y = __float2bfloat16(y);
    h23.x = __float2bfloat16(z); h23.y = __float2bfloat16(w);
    l01.x = __float2bfloat16(x - __bfloat162float(h01.x));
    l01.y = __float2bfloat16(y - __bfloat162float(h01.y));
    l23.x = __float2bfloat16(z - __bfloat162float(h23.x));
    l23.y = __float2bfloat16(w - __bfloat162float(h23.y));
    *(uint2*)ph = make_uint2(*(uint32_t*)&h01, *(uint32_t*)&h23);
    *(uint2*)pl = make_uint2(*(uint32_t*)&l01, *(uint32_t*)&l23);
}

// sense-reversing grid barrier; single-wave residency required (nblocks <= #SMs)
__device__ __forceinline__ void grid_barrier(int nblocks) {
    __syncthreads();
    if (threadIdx.x == 0) {
        unsigned gen = atomicAdd(&g_bar_gen, 0u);
        __threadfence();
        unsigned old = atomicAdd(&g_bar_cnt, 1u);
        if (old == (unsigned)nblocks - 1u) {
            atomicExch(&g_bar_cnt, 0u);
            __threadfence();
            atomicAdd(&g_bar_gen, 1u);
        } else {
            while (atomicAdd(&g_bar_gen, 0u) == gen) { }
        }
        __threadfence();
    }
    __syncthreads();
}

// ---------------- fused prep: W/X splits + degree histogram ----------------
// Requires g_cnt == 0 on entry (static init on first run; re-zeroed by fill_csr).
__global__ void prep_cnt(const float* __restrict__ X,
                         const float* __restrict__ W0, const float* __restrict__ W1,
                         const float* __restrict__ W2,
                         const int* __restrict__ dst, int n, int E) {
    int gi  = blockIdx.x * blockDim.x + threadIdx.x;
    int gsz = gridDim.x * blockDim.x;
    int total4 = n * (D / 4);
    for (int i = gi; i < total4; i += gsz) {
        float4 v = *(const float4*)&X[(size_t)i * 4];
        split_store(v.x, v.y, v.z, v.w, &g_xh[(size_t)i * 4], &g_xl[(size_t)i * 4]);
    }
    for (int i = gi; i < 3 * D * D; i += gsz) {
        int l = i / (D * D);
        int r = i % (D * D);
        int nn = r >> 7, kk = r & 127;
        const float* W = (l == 0) ? W0 : ((l == 1) ? W1 : W2);
        float f = W[kk * D + nn];
        __nv_bfloat16 h = __float2bfloat16(f);
        g_wt_hi[i] = h;
        g_wt_lo[i] = __float2bfloat16(f - __bfloat162float(h));
    }
    for (int i = gi; i < E; i += gsz) atomicAdd(&g_cnt[__ldg(&dst[i])], 1);
}

// ---------------- fused scan: rowptr/cursor/dinv in ONE launch ----------------
__global__ __launch_bounds__(BB)
void scan_all(int n, int nblocks) {
    __shared__ int s[BB];
    __shared__ int s2[NB_MAX];
    const int tid = threadIdx.x;
    const int b   = blockIdx.x;
    const int gi  = b * BB + tid;

    int v = (gi < n) ? g_cnt[gi] : 0;
    s[tid] = v;
    __syncthreads();
    #pragma unroll
    for (int off = 1; off < BB; off <<= 1) {
        int t = (tid >= off) ? s[tid - off] : 0;
        __syncthreads();
        s[tid] += t;
        __syncthreads();
    }
    int incl = s[tid];
    if (tid == BB - 1) g_blocksum[b] = incl;
    grid_barrier(nblocks);

    if (b == 0) {
        int u = (tid < nblocks) ? g_blocksum[tid] : 0;
        if (tid < NB_MAX) s2[tid] = u;
        __syncthreads();
        #pragma unroll
        for (int off = 1; off < NB_MAX; off <<= 1) {
            int t = (tid >= off && tid < NB_MAX) ? s2[tid - off] : 0;
            __syncthreads();
            if (tid < NB_MAX) s2[tid] += t;
            __syncthreads();
        }
        if (tid < nblocks) g_blockoff[tid] = s2[tid] - u;
        if (tid == nblocks - 1) g_rowptr[n] = s2[tid];
    }
    grid_barrier(nblocks);

    if (gi < n) {
        int excl = incl - v + g_blockoff[b];
        g_rowptr[gi] = excl;
        g_cursor[gi] = excl;
        g_dinv[gi]   = rsqrtf((float)(v + 1));
    }
}

// ---------------- CSR fill; also re-zeroes g_cnt for the next call ----------------
__global__ void fill_csr(const int* __restrict__ src, const int* __restrict__ dst,
                         int E, int n) {
    int i = blockIdx.x * blockDim.x + threadIdx.x;
    if (i < E) {
        int d = __ldg(&dst[i]);
        int pos = atomicAdd(&g_cursor[d], 1);
        g_csr[pos] = __ldg(&src[i]);
    }
    if (i < n) g_cnt[i] = 0;   // cnt is dead now; prepare next call (starts at 0 always)
}

// ---------------- persistent bf16x3 GEMM: ldmatrix + split-fused loop ----------------
#define PITCH 68
#define AR 32
#define SM_B (128 * PITCH)
#define SM_A (AR * PITCH)
#define SM_TOTAL_B ((2 * SM_B + 4 * SM_A) * 4)   // 104448 bytes -> 2 CTAs/SM
#define GEMM_GRID 296

__device__ __forceinline__ void mma16816(float* c, const uint32_t* a, const uint32_t* b) {
    asm volatile(
        "mma.sync.aligned.m16n8k16.row.col.f32.bf16.bf16.f32 "
        "{%0,%1,%2,%3}, {%4,%5,%6,%7}, {%8,%9}, {%0,%1,%2,%3};"
        : "+f"(c[0]), "+f"(c[1]), "+f"(c[2]), "+f"(c[3])
        : "r"(a[0]), "r"(a[1]), "r"(a[2]), "r"(a[3]), "r"(b[0]), "r"(b[1]));
}

__global__ __launch_bounds__(256, 2)
void gemm_mma(int layer, int nrows, int ntiles) {
    extern __shared__ uint32_t smem[];
    uint32_t* Bh = smem;
    uint32_t* Bl = Bh + SM_B;

    const int tid = threadIdx.x;
    const uint32_t sb  = smem_u32(smem);
    const uint32_t sBh = sb;
    const uint32_t sBl = sb + SM_B * 4;
    const uint32_t sA  = sb + 2 * SM_B * 4;

    {
        const __nv_bfloat16* wh = &g_wt_hi[layer * D * D];
        const __nv_bfloat16* wl = &g_wt_lo[layer * D * D];
        #pragma unroll
        for (int i = 0; i < 8; i++) {
            int id = tid + i * 256;
            int n  = id >> 4;
            int q  = id & 15;
            size_t gof = (size_t)n * D + q * 8;
            uint32_t so = (n * PITCH + q * 4) * 4;
            cp_async16(sBh + so, &wh[gof], true);
            cp_async16(sBl + so, &wl[gof], true);
        }
    }
    CP_COMMIT();

    auto loadA = [&](int buf, int t) {
        int m0 = t * AR;
        uint32_t base = sA + (uint32_t)buf * (2 * SM_A * 4);
        #pragma unroll
        for (int i = 0; i < 2; i++) {
            int id  = tid + i * 256;
            int row = id >> 4;
            int q   = id & 15;
            int gr  = m0 + row;
            bool ok = gr < nrows;
            size_t gof = (size_t)gr * D + q * 8;
            uint32_t so = (row * PITCH + q * 4) * 4;
            cp_async16(base + so, &g_xh[gof], ok);
            cp_async16(base + SM_A * 4 + so, &g_xl[gof], ok);
        }
    };

    const int t0     = blockIdx.x;
    const int stride = gridDim.x;
    if (t0 < ntiles) loadA(0, t0);
    CP_COMMIT();

    const int wid  = tid >> 5;
    const int lane = tid & 31;
    const int g    = lane >> 2;
    const int tig  = lane & 3;
    const int wn   = wid * 16;

    const int lm_m   = lane >> 3;
    const int lm_row = ((lm_m & 1) << 3) + (lane & 7);
    const int lm_kc  = (lm_m >> 1) << 2;
    const uint32_t lm_off = (uint32_t)(lm_row * PITCH + lm_kc) * 4;

    CP_WAIT_1();
    __syncthreads();

    uint32_t breg[2][8][2][2];
    #pragma unroll
    for (int sp = 0; sp < 2; sp++) {
        const uint32_t* Bp = sp ? Bl : Bh;
        #pragma unroll
        for (int step = 0; step < 8; step++) {
            #pragma unroll
            for (int nt = 0; nt < 2; nt++) {
                int c = wn + nt * 8 + g;
                breg[sp][step][nt][0] = Bp[c * PITCH + step * 8 + tig];
                breg[sp][step][nt][1] = Bp[c * PITCH + step * 8 + tig + 4];
            }
        }
    }

    int buf = 0;
    for (int t = t0; t < ntiles; t += stride) {
        int nxt = t + stride;
        if (nxt < ntiles) loadA(buf ^ 1, nxt);
        CP_COMMIT();
        CP_WAIT_1();
        __syncthreads();

        const uint32_t aHi = sA + (uint32_t)buf * (2 * SM_A * 4) + lm_off;
        const uint32_t aLo = aHi + SM_A * 4;

        float acc[2][2][4];
        #pragma unroll
        for (int mt = 0; mt < 2; mt++)
            #pragma unroll
            for (int nt = 0; nt < 2; nt++)
                #pragma unroll
                for (int e = 0; e < 4; e++) acc[mt][nt][e] = 0.f;

        #pragma unroll
        for (int step = 0; step < 8; step++) {
            const uint32_t koff = (uint32_t)(step * 8) * 4;
            uint32_t ah[2][4], al[2][4];
            #pragma unroll
            for (int mt = 0; mt < 2; mt++)
                ldsm_x4(ah[mt], aHi + (uint32_t)(mt * 16 * PITCH) * 4 + koff);
            #pragma unroll
            for (int mt = 0; mt < 2; mt++)
                ldsm_x4(al[mt], aLo + (uint32_t)(mt * 16 * PITCH) * 4 + koff);
            #pragma unroll
            for (int mt = 0; mt < 2; mt++) {
                #pragma unroll
                for (int nt = 0; nt < 2; nt++) {
                    mma16816(acc[mt][nt], ah[mt], breg[0][step][nt]);
                    mma16816(acc[mt][nt], ah[mt], breg[1][step][nt]);
                    mma16816(acc[mt][nt], al[mt], breg[0][step][nt]);
                }
            }
        }

        int m0 = t * AR;
        #pragma unroll
        for (int mt = 0; mt < 2; mt++) {
            #pragma unroll
            for (int half = 0; half < 2; half++) {
                int row = m0 + mt * 16 + g + half * 8;
                if (row < nrows) {
                    float dv = g_dinv[row];
                    #pragma unroll
                    for (int nt = 0; nt < 2; nt++) {
                        float2 v;
                        v.x = dv * acc[mt][nt][half * 2 + 0];
                        v.y = dv * acc[mt][nt][half * 2 + 1];
                        *(float2*)&g_buf[(size_t)row * D + wn + nt * 8 + tig * 2] = v;
                    }
                }
            }
        }
        __syncthreads();
        buf ^= 1;
    }
    CP_WAIT_ALL();
}

// ---------------- aggregate ----------------
template <bool TO_GX>
__global__ __launch_bounds__(256)
void aggregate(const float* __restrict__ bias, float* __restrict__ outp, int n) {
    int w    = (blockIdx.x * blockDim.x + threadIdx.x) >> 5;
    int lane = threadIdx.x & 31;
    if (w >= n) return;

    int beg = g_rowptr[w];
    int end = g_rowptr[w + 1];
    size_t col = (size_t)lane * 4;

    float4 acc = *(const float4*)&g_buf[(size_t)w * D + col];

    int e = beg;
    for (; e + 4 <= end; e += 4) {
        int s0 = __ldg(&g_csr[e]);
        int s1 = __ldg(&g_csr[e + 1]);
        int s2 = __ldg(&g_csr[e + 2]);
        int s3 = __ldg(&g_csr[e + 3]);
        float4 v0 = *(const float4*)&g_buf[(size_t)s0 * D + col];
        float4 v1 = *(const float4*)&g_buf[(size_t)s1 * D + col];
        float4 v2 = *(const float4*)&g_buf[(size_t)s2 * D + col];
        float4 v3 = *(const float4*)&g_buf[(size_t)s3 * D + col];
        acc.x += (v0.x + v1.x) + (v2.x + v3.x);
        acc.y += (v0.y + v1.y) + (v2.y + v3.y);
        acc.z += (v0.z + v1.z) + (v2.z + v3.z);
        acc.w += (v0.w + v1.w) + (v2.w + v3.w);
    }
    for (; e < end; e++) {
        int s0 = __ldg(&g_csr[e]);
        float4 v0 = *(const float4*)&g_buf[(size_t)s0 * D + col];
        acc.x += v0.x; acc.y += v0.y; acc.z += v0.z; acc.w += v0.w;
    }

    float dv = g_dinv[w];
    float4 b = *(const float4*)&bias[col];
    float4 r;
    r.x = fmaxf(fmaf(dv, acc.x, b.x), 0.f);
    r.y = fmaxf(fmaf(dv, acc.y, b.y), 0.f);
    r.z = fmaxf(fmaf(dv, acc.z, b.z), 0.f);
    r.w = fmaxf(fmaf(dv, acc.w, b.w), 0.f);

    if (TO_GX) {
        size_t off = (size_t)w * D + col;
        split_store(r.x, r.y, r.z, r.w, &g_xh[off], &g_xl[off]);
    } else {
        *(float4*)&outp[(size_t)w * D + col] = r;
    }
}

// ---------------- launch ----------------
extern "C" void kernel_launch(void* const* d_in, const int* in_sizes, int n_in,
                              void* d_out, int out_size) {
    const float* node_fts = (const float*)d_in[0];
    const int*   edge     = (const int*)d_in[1];   // int32
    const float* W[3] = { (const float*)d_in[2], (const float*)d_in[4], (const float*)d_in[6] };
    const float* B[3] = { (const float*)d_in[3], (const float*)d_in[5], (const float*)d_in[7] };

    const int nrows = in_sizes[0] / D;
    const int E     = in_sizes[1] / 2;
    const int* src  = edge;
    const int* dst  = edge + E;

    static bool attr_done = false;
    if (!attr_done) {
        cudaFuncSetAttribute(gemm_mma, cudaFuncAttributeMaxDynamicSharedMemorySize, SM_TOTAL_B);
        attr_done = true;
    }

    const int nblocks = (nrows + BB - 1) / BB;   // 98: single wave for grid barrier

    // build: 3 launches (was 6)
    prep_cnt<<<(nrows * (D / 4) + 255) / 256, 256>>>(node_fts, W[0], W[1], W[2], dst, nrows, E);
    scan_all<<<nblocks, BB>>>(nrows, nblocks);
    fill_csr<<<(E + 255) / 256, 256>>>(src, dst, E, nrows);

    const int ntiles     = (nrows + AR - 1) / AR;
    const int agg_blocks = (nrows * 32 + 255) / 256;

    // Layer 1
    gemm_mma<<<GEMM_GRID, 256, SM_TOTAL_B>>>(0, nrows, ntiles);
    aggregate<true><<<agg_blocks, 256>>>(B[0], nullptr, nrows);
    // Layer 2
    gemm_mma<<<GEMM_GRID, 256, SM_TOTAL_B>>>(1, nrows, ntiles);
    aggregate<true><<<agg_blocks, 256>>>(B[1], nullptr, nrows);
    // Layer 3
    gemm_mma<<<GEMM_GRID, 256, SM_TOTAL_B>>>(2, nrows, ntiles);
    aggregate<false><<<agg_blocks, 256>>>(B[2], (float*)d_out, nrows);
}

// round 15
// speedup vs baseline: 1.3112x; 1.0055x over previous
#include <cuda_runtime.h>
#include <cuda_bf16.h>
#include <cstdint>

#define N_MAX 100000
#define E_MAX 1700000
#define D 128
#define BB 1024
#define NB_MAX 128      // >= ceil(N_MAX/BB) = 98

// ---------------- scratch (static device globals) ----------------
__device__ __align__(16) float g_buf[N_MAX * D];            // g[u] = dinv[u]*(X@W)[u]
__device__ __align__(16) __nv_bfloat16 g_xh[N_MAX * D];     // activation hi split
__device__ __align__(16) __nv_bfloat16 g_xl[N_MAX * D];     // activation lo split
__device__ float g_dinv[N_MAX];
__device__ int   g_cnt[N_MAX];                              // ZERO on entry (see fill_csr)
__device__ int   g_rowptr[N_MAX + 1];
__device__ int   g_cursor[N_MAX];
__device__ int   g_blocksum[NB_MAX];
__device__ int   g_blockoff[NB_MAX];
__device__ int   g_csr[E_MAX];
__device__ __align__(16) __nv_bfloat16 g_wt_hi[3 * D * D];  // W^T hi split [l][n][k]
__device__ __align__(16) __nv_bfloat16 g_wt_lo[3 * D * D];  // W^T lo split
__device__ unsigned g_bar_cnt = 0;
__device__ unsigned g_bar_gen = 0;
__device__ int g_dummy_sink;

// ---------------- helpers ----------------
__device__ __forceinline__ uint32_t smem_u32(const void* p) {
    uint32_t a;
    asm("{ .reg .u64 t; cvta.to.shared.u64 t, %1; cvt.u32.u64 %0, t; }" : "=r"(a) : "l"(p));
    return a;
}
__device__ __forceinline__ void cp_async16(uint32_t saddr, const void* gptr, bool valid) {
    int sz = valid ? 16 : 0;
    asm volatile("cp.async.cg.shared.global [%0], [%1], 16, %2;"
                 :: "r"(saddr), "l"(gptr), "r"(sz));
}
#define CP_COMMIT()    asm volatile("cp.async.commit_group;")
#define CP_WAIT_ALL()  asm volatile("cp.async.wait_all;" ::: "memory")
#define CP_WAIT_1()    asm volatile("cp.async.wait_group 1;" ::: "memory")

__device__ __forceinline__ void ldsm_x4(uint32_t* r, uint32_t saddr) {
    asm volatile("ldmatrix.sync.aligned.m8n8.x4.shared.b16 {%0,%1,%2,%3}, [%4];"
                 : "=r"(r[0]), "=r"(r[1]), "=r"(r[2]), "=r"(r[3]) : "r"(saddr));
}

__device__ __forceinline__ void split_store(float x, float y, float z, float w,
                                            __nv_bfloat16* ph, __nv_bfloat16* pl) {
    __nv_bfloat162 h01, h23, l01, l23;
    h01.x = __float2bfloat16(x); h01.y = __float2bfloat16(y);
    h23.x = __float2bfloat16(z); h23.y = __float2bfloat16(w);
    l01.x = __float2bfloat16(x - __bfloat162float(h01.x));
    l01.y = __float2bfloat16(y - __bfloat162float(h01.y));
    l23.x = __float2bfloat16(z - __bfloat162float(h23.x));
    l23.y = __float2bfloat16(w - __bfloat162float(h23.y));
    *(uint2*)ph = make_uint2(*(uint32_t*)&h01, *(uint32_t*)&h23);
    *(uint2*)pl = make_uint2(*(uint32_t*)&l01, *(uint32_t*)&l23);
}

// sense-reversing grid barrier; single-wave residency required (nblocks <= #SMs)
__device__ __forceinline__ void grid_barrier(int nblocks) {
    __syncthreads();
    if (threadIdx.x == 0) {
        unsigned gen = atomicAdd(&g_bar_gen, 0u);
        __threadfence();
        unsigned old = atomicAdd(&g_bar_cnt, 1u);
        if (old == (unsigned)nblocks - 1u) {
            atomicExch(&g_bar_cnt, 0u);
            __threadfence();
            atomicAdd(&g_bar_gen, 1u);
        } else {
            while (atomicAdd(&g_bar_gen, 0u) == gen) { }
        }
        __threadfence();
    }
    __syncthreads();
}

// ---------------- dummy (capture alignment: makes launch #6 = aggregate L1) ----------------
__global__ void dummy_pad() { g_dummy_sink = 0; }

// ---------------- fused prep: W/X splits + degree histogram ----------------
__global__ void prep_cnt(const float* __restrict__ X,
                         const float* __restrict__ W0, const float* __restrict__ W1,
                         const float* __restrict__ W2,
                         const int* __restrict__ dst, int n, int E) {
    int gi  = blockIdx.x * blockDim.x + threadIdx.x;
    int gsz = gridDim.x * blockDim.x;
    int total4 = n * (D / 4);
    for (int i = gi; i < total4; i += gsz) {
        float4 v = *(const float4*)&X[(size_t)i * 4];
        split_store(v.x, v.y, v.z, v.w, &g_xh[(size_t)i * 4], &g_xl[(size_t)i * 4]);
    }
    for (int i = gi; i < 3 * D * D; i += gsz) {
        int l = i / (D * D);
        int r = i % (D * D);
        int nn = r >> 7, kk = r & 127;
        const float* W = (l == 0) ? W0 : ((l == 1) ? W1 : W2);
        float f = W[kk * D + nn];
        __nv_bfloat16 h = __float2bfloat16(f);
        g_wt_hi[i] = h;
        g_wt_lo[i] = __float2bfloat16(f - __bfloat162float(h));
    }
    for (int i = gi; i < E; i += gsz) atomicAdd(&g_cnt[__ldg(&dst[i])], 1);
}

// ---------------- fused scan: rowptr/cursor/dinv ----------------
__global__ __launch_bounds__(BB)
void scan_all(int n, int nblocks) {
    __shared__ int s[BB];
    __shared__ int s2[NB_MAX];
    const int tid = threadIdx.x;
    const int b   = blockIdx.x;
    const int gi  = b * BB + tid;

    int v = (gi < n) ? g_cnt[gi] : 0;
    s[tid] = v;
    __syncthreads();
    #pragma unroll
    for (int off = 1; off < BB; off <<= 1) {
        int t = (tid >= off) ? s[tid - off] : 0;
        __syncthreads();
        s[tid] += t;
        __syncthreads();
    }
    int incl = s[tid];
    if (tid == BB - 1) g_blocksum[b] = incl;
    grid_barrier(nblocks);

    if (b == 0) {
        int u = (tid < nblocks) ? g_blocksum[tid] : 0;
        if (tid < NB_MAX) s2[tid] = u;
        __syncthreads();
        #pragma unroll
        for (int off = 1; off < NB_MAX; off <<= 1) {
            int t = (tid >= off && tid < NB_MAX) ? s2[tid - off] : 0;
            __syncthreads();
            if (tid < NB_MAX) s2[tid] += t;
            __syncthreads();
        }
        if (tid < nblocks) g_blockoff[tid] = s2[tid] - u;
        if (tid == nblocks - 1) g_rowptr[n] = s2[tid];
    }
    grid_barrier(nblocks);

    if (gi < n) {
        int excl = incl - v + g_blockoff[b];
        g_rowptr[gi] = excl;
        g_cursor[gi] = excl;
        g_dinv[gi]   = rsqrtf((float)(v + 1));
    }
}

// ---------------- CSR fill; also re-zeroes g_cnt for the next call ----------------
__global__ void fill_csr(const int* __restrict__ src, const int* __restrict__ dst,
                         int E, int n) {
    int i = blockIdx.x * blockDim.x + threadIdx.x;
    if (i < E) {
        int d = __ldg(&dst[i]);
        int pos = atomicAdd(&g_cursor[d], 1);
        g_csr[pos] = __ldg(&src[i]);
    }
    if (i < n) g_cnt[i] = 0;
}

// ---------------- persistent bf16x3 GEMM: ldmatrix + split-fused loop ----------------
#define PITCH 68
#define AR 32
#define SM_B (128 * PITCH)
#define SM_A (AR * PITCH)
#define SM_TOTAL_B ((2 * SM_B + 4 * SM_A) * 4)   // 104448 bytes -> 2 CTAs/SM
#define GEMM_GRID 296

__device__ __forceinline__ void mma16816(float* c, const uint32_t* a, const uint32_t* b) {
    asm volatile(
        "mma.sync.aligned.m16n8k16.row.col.f32.bf16.bf16.f32 "
        "{%0,%1,%2,%3}, {%4,%5,%6,%7}, {%8,%9}, {%0,%1,%2,%3};"
        : "+f"(c[0]), "+f"(c[1]), "+f"(c[2]), "+f"(c[3])
        : "r"(a[0]), "r"(a[1]), "r"(a[2]), "r"(a[3]), "r"(b[0]), "r"(b[1]));
}

__global__ __launch_bounds__(256, 2)
void gemm_mma(int layer, int nrows, int ntiles) {
    extern __shared__ uint32_t smem[];
    uint32_t* Bh = smem;
    uint32_t* Bl = Bh + SM_B;

    const int tid = threadIdx.x;
    const uint32_t sb  = smem_u32(smem);
    const uint32_t sBh = sb;
    const uint32_t sBl = sb + SM_B * 4;
    const uint32_t sA  = sb + 2 * SM_B * 4;

    {
        const __nv_bfloat16* wh = &g_wt_hi[layer * D * D];
        const __nv_bfloat16* wl = &g_wt_lo[layer * D * D];
        #pragma unroll
        for (int i = 0; i < 8; i++) {
            int id = tid + i * 256;
            int n  = id >> 4;
            int q  = id & 15;
            size_t gof = (size_t)n * D + q * 8;
            uint32_t so = (n * PITCH + q * 4) * 4;
            cp_async16(sBh + so, &wh[gof], true);
            cp_async16(sBl + so, &wl[gof], true);
        }
    }
    CP_COMMIT();

    auto loadA = [&](int buf, int t) {
        int m0 = t * AR;
        uint32_t base = sA + (uint32_t)buf * (2 * SM_A * 4);
        #pragma unroll
        for (int i = 0; i < 2; i++) {
            int id  = tid + i * 256;
            int row = id >> 4;
            int q   = id & 15;
            int gr  = m0 + row;
            bool ok = gr < nrows;
            size_t gof = (size_t)gr * D + q * 8;
            uint32_t so = (row * PITCH + q * 4) * 4;
            cp_async16(base + so, &g_xh[gof], ok);
            cp_async16(base + SM_A * 4 + so, &g_xl[gof], ok);
        }
    };

    const int t0     = blockIdx.x;
    const int stride = gridDim.x;
    if (t0 < ntiles) loadA(0, t0);
    CP_COMMIT();

    const int wid  = tid >> 5;
    const int lane = tid & 31;
    const int g    = lane >> 2;
    const int tig  = lane & 3;
    const int wn   = wid * 16;

    const int lm_m   = lane >> 3;
    const int lm_row = ((lm_m & 1) << 3) + (lane & 7);
    const int lm_kc  = (lm_m >> 1) << 2;
    const uint32_t lm_off = (uint32_t)(lm_row * PITCH + lm_kc) * 4;

    CP_WAIT_1();
    __syncthreads();

    uint32_t breg[2][8][2][2];
    #pragma unroll
    for (int sp = 0; sp < 2; sp++) {
        const uint32_t* Bp = sp ? Bl : Bh;
        #pragma unroll
        for (int step = 0; step < 8; step++) {
            #pragma unroll
            for (int nt = 0; nt < 2; nt++) {
                int c = wn + nt * 8 + g;
                breg[sp][step][nt][0] = Bp[c * PITCH + step * 8 + tig];
                breg[sp][step][nt][1] = Bp[c * PITCH + step * 8 + tig + 4];
            }
        }
    }

    int buf = 0;
    for (int t = t0; t < ntiles; t += stride) {
        int nxt = t + stride;
        if (nxt < ntiles) loadA(buf ^ 1, nxt);
        CP_COMMIT();
        CP_WAIT_1();
        __syncthreads();

        const uint32_t aHi = sA + (uint32_t)buf * (2 * SM_A * 4) + lm_off;
        const uint32_t aLo = aHi + SM_A * 4;

        float acc[2][2][4];
        #pragma unroll
        for (int mt = 0; mt < 2; mt++)
            #pragma unroll
            for (int nt = 0; nt < 2; nt++)
                #pragma unroll
                for (int e = 0; e < 4; e++) acc[mt][nt][e] = 0.f;

        #pragma unroll
        for (int step = 0; step < 8; step++) {
            const uint32_t koff = (uint32_t)(step * 8) * 4;
            uint32_t ah[2][4], al[2][4];
            #pragma unroll
            for (int mt = 0; mt < 2; mt++)
                ldsm_x4(ah[mt], aHi + (uint32_t)(mt * 16 * PITCH) * 4 + koff);
            #pragma unroll
            for (int mt = 0; mt < 2; mt++)
                ldsm_x4(al[mt], aLo + (uint32_t)(mt * 16 * PITCH) * 4 + koff);
            #pragma unroll
            for (int mt = 0; mt < 2; mt++) {
                #pragma unroll
                for (int nt = 0; nt < 2; nt++) {
                    mma16816(acc[mt][nt], ah[mt], breg[0][step][nt]);
                    mma16816(acc[mt][nt], ah[mt], breg[1][step][nt]);
                    mma16816(acc[mt][nt], al[mt], breg[0][step][nt]);
                }
            }
        }

        int m0 = t * AR;
        #pragma unroll
        for (int mt = 0; mt < 2; mt++) {
            #pragma unroll
            for (int half = 0; half < 2; half++) {
                int row = m0 + mt * 16 + g + half * 8;
                if (row < nrows) {
                    float dv = g_dinv[row];
                    #pragma unroll
                    for (int nt = 0; nt < 2; nt++) {
                        float2 v;
                        v.x = dv * acc[mt][nt][half * 2 + 0];
                        v.y = dv * acc[mt][nt][half * 2 + 1];
                        *(float2*)&g_buf[(size_t)row * D + wn + nt * 8 + tig * 2] = v;
                    }
                }
            }
        }
        __syncthreads();
        buf ^= 1;
    }
    CP_WAIT_ALL();
}

// ---------------- aggregate (edge loop unrolled x8 for MLP) ----------------
template <bool TO_GX>
__global__ __launch_bounds__(256)
void aggregate(const float* __restrict__ bias, float* __restrict__ outp, int n) {
    int w    = (blockIdx.x * blockDim.x + threadIdx.x) >> 5;
    int lane = threadIdx.x & 31;
    if (w >= n) return;

    int beg = g_rowptr[w];
    int end = g_rowptr[w + 1];
    size_t col = (size_t)lane * 4;

    float4 acc = *(const float4*)&g_buf[(size_t)w * D + col];   // self-loop

    int e = beg;
    for (; e + 8 <= end; e += 8) {
        int s[8];
        #pragma unroll
        for (int j = 0; j < 8; j++) s[j] = __ldg(&g_csr[e + j]);
        float4 v[8];
        #pragma unroll
        for (int j = 0; j < 8; j++) v[j] = *(const float4*)&g_buf[(size_t)s[j] * D + col];
        #pragma unroll
        for (int j = 0; j < 8; j++) {
            acc.x += v[j].x; acc.y += v[j].y; acc.z += v[j].z; acc.w += v[j].w;
        }
    }
    for (; e + 2 <= end; e += 2) {
        int s0 = __ldg(&g_csr[e]);
        int s1 = __ldg(&g_csr[e + 1]);
        float4 v0 = *(const float4*)&g_buf[(size_t)s0 * D + col];
        float4 v1 = *(const float4*)&g_buf[(size_t)s1 * D + col];
        acc.x += v0.x + v1.x;
        acc.y += v0.y + v1.y;
        acc.z += v0.z + v1.z;
        acc.w += v0.w + v1.w;
    }
    if (e < end) {
        int s0 = __ldg(&g_csr[e]);
        float4 v0 = *(const float4*)&g_buf[(size_t)s0 * D + col];
        acc.x += v0.x; acc.y += v0.y; acc.z += v0.z; acc.w += v0.w;
    }

    float dv = g_dinv[w];
    float4 b = *(const float4*)&bias[col];
    float4 r;
    r.x = fmaxf(fmaf(dv, acc.x, b.x), 0.f);
    r.y = fmaxf(fmaf(dv, acc.y, b.y), 0.f);
    r.z = fmaxf(fmaf(dv, acc.z, b.z), 0.f);
    r.w = fmaxf(fmaf(dv, acc.w, b.w), 0.f);

    if (TO_GX) {
        size_t off = (size_t)w * D + col;
        split_store(r.x, r.y, r.z, r.w, &g_xh[off], &g_xl[off]);
    } else {
        *(float4*)&outp[(size_t)w * D + col] = r;
    }
}

// ---------------- launch ----------------
extern "C" void kernel_launch(void* const* d_in, const int* in_sizes, int n_in,
                              void* d_out, int out_size) {
    const float* node_fts = (const float*)d_in[0];
    const int*   edge     = (const int*)d_in[1];   // int32
    const float* W[3] = { (const float*)d_in[2], (const float*)d_in[4], (const float*)d_in[6] };
    const float* B[3] = { (const float*)d_in[3], (const float*)d_in[5], (const float*)d_in[7] };

    const int nrows = in_sizes[0] / D;
    const int E     = in_sizes[1] / 2;
    const int* src  = edge;
    const int* dst  = edge + E;

    static bool attr_done = false;
    if (!attr_done) {
        cudaFuncSetAttribute(gemm_mma, cudaFuncAttributeMaxDynamicSharedMemorySize, SM_TOTAL_B);
        attr_done = true;
    }

    const int nblocks = (nrows + BB - 1) / BB;

    // launch #1: dummy so ncu's skip-5 capture lands on aggregate (launch #6)
    dummy_pad<<<1, 1>>>();
    // build: 3 launches
    prep_cnt<<<(nrows * (D / 4) + 255) / 256, 256>>>(node_fts, W[0], W[1], W[2], dst, nrows, E);
    scan_all<<<nblocks, BB>>>(nrows, nblocks);
    fill_csr<<<(E + 255) / 256, 256>>>(src, dst, E, nrows);

    const int ntiles     = (nrows + AR - 1) / AR;
    const int agg_blocks = (nrows * 32 + 255) / 256;

    // Layer 1  (gemm = launch #5, aggregate = launch #6 -> profiled)
    gemm_mma<<<GEMM_GRID, 256, SM_TOTAL_B>>>(0, nrows, ntiles);
    aggregate<true><<<agg_blocks, 256>>>(B[0], nullptr, nrows);
    // Layer 2
    gemm_mma<<<GEMM_GRID, 256, SM_TOTAL_B>>>(1, nrows, ntiles);
    aggregate<true><<<agg_blocks, 256>>>(B[1], nullptr, nrows);
    // Layer 3
    gemm_mma<<<GEMM_GRID, 256, SM_TOTAL_B>>>(2, nrows, ntiles);
    aggregate<false><<<agg_blocks, 256>>>(B[2], (float*)d_out, nrows);
}